// round 1
// baseline (speedup 1.0000x reference)
#include <cuda_runtime.h>
#include <math.h>
#include <stdint.h>

#define B_    4
#define C_    384
#define H_    224
#define HH_   28
#define N_    784
#define HEADS 8
#define HD    48

#define AFF_SCALE  0.05103103630798288f   /* 384^-0.5 */
#define ATTN_SCALE 0.14433756729740643f   /* 48^-0.5 */

// ------------------------- scratch (device globals, no allocs) -------------
__device__ float g_sf[B_ * N_ * C_];              // (B, site, C)
__device__ float g_aff[B_ * N_ * 64 * 9];         // (B, n, p, k)
__device__ float g_affsum[B_ * N_ * 9];           // (B, n, k)
__device__ float g_sft_site[B_ * N_ * 9 * C_];    // (B, n, k, C)
__device__ float g_sftn[B_ * N_ * C_];            // (B, n, C)
__device__ float g_qkv[B_ * 3 * C_ * N_];         // (B, o, n)
__device__ float g_attno[B_ * N_ * C_];           // (B, n, C)
__device__ float g_projo[B_ * N_ * C_];           // (B, n, C)

// ------------------------- 1) 8x8 average pool -----------------------------
// block = (y, c, b), 224 threads (one per column)
__global__ void pool_kernel(const float* __restrict__ xs) {
    int y = blockIdx.x, c = blockIdx.y, b = blockIdx.z;
    int t = threadIdx.x;  // 0..223
    const float* base = xs + ((size_t)(b * C_ + c) * H_ + (size_t)y * 8) * H_;
    float s = 0.f;
#pragma unroll
    for (int dy = 0; dy < 8; dy++) s += base[dy * H_ + t];
    __shared__ float sm[224];
    sm[t] = s;
    __syncthreads();
    if (t < HH_) {
        float acc = 0.f;
#pragma unroll
        for (int i = 0; i < 8; i++) acc += sm[t * 8 + i];
        g_sf[((size_t)b * N_ + (size_t)y * HH_ + t) * C_ + c] = acc * (1.0f / 64.0f);
    }
}

// ------------------------- 2) per-site affinity + aggregation --------------
// grid (784, 4), 384 threads, dynamic smem ~130KB
#define SITE_SMEM_FLOATS (C_ * 65 + C_ * 9 + 6 * 576 + 576)
__global__ void site_kernel(const float* __restrict__ xs) {
    extern __shared__ float sm[];
    float* pix   = sm;                 // [c*65 + p]   (pad 65: conflict-free both ways)
    float* sf9   = pix + C_ * 65;      // [c*9 + k]
    float* lpart = sf9 + C_ * 9;       // [chunk*576 + p*9 + k]
    float* aff_s = lpart + 6 * 576;    // [p*9 + k]

    int n = blockIdx.x, b = blockIdx.y;
    int y = n / HH_, x = n % HH_;
    int tid = threadIdx.x;

    // load 64x384 pixel tile (float4, coalesced)
    const float* xbase = xs + ((size_t)b * C_ * H_ + (size_t)y * 8) * H_ + (size_t)x * 8;
    for (int q = tid; q < C_ * 16; q += 384) {
        int c = q >> 4, r = q & 15;
        int py = r >> 1, pxq = (r & 1) << 2;
        float4 v = *(const float4*)(xbase + ((size_t)c * H_ + py) * H_ + pxq);
        int p = py * 8 + pxq;
        pix[c * 65 + p + 0] = v.x;
        pix[c * 65 + p + 1] = v.y;
        pix[c * 65 + p + 2] = v.z;
        pix[c * 65 + p + 3] = v.w;
    }
    // load 3x3 neighborhood of sf (unfold): sf9[c][k] = sf[y+i-1, x+j-1]
#pragma unroll
    for (int k = 0; k < 9; k++) {
        int yy = y + k / 3 - 1, xx = x + k % 3 - 1;
        float v = 0.f;
        if (yy >= 0 && yy < HH_ && xx >= 0 && xx < HH_)
            v = g_sf[((size_t)b * N_ + yy * HH_ + xx) * C_ + tid];
        sf9[tid * 9 + k] = v;
    }
    __syncthreads();

    // logits: split C over 6 chunks of 64
    {
        int p = tid & 63, chunk = tid >> 6;
        float acc[9];
#pragma unroll
        for (int k = 0; k < 9; k++) acc[k] = 0.f;
        for (int cc = 0; cc < 64; cc++) {
            int c = (chunk << 6) + cc;
            float pv = pix[c * 65 + p];
#pragma unroll
            for (int k = 0; k < 9; k++) acc[k] += pv * sf9[c * 9 + k];
        }
#pragma unroll
        for (int k = 0; k < 9; k++) lpart[chunk * 576 + p * 9 + k] = acc[k];
    }
    __syncthreads();
    for (int idx = tid; idx < 576; idx += 384) {
        float s = 0.f;
#pragma unroll
        for (int ch = 0; ch < 6; ch++) s += lpart[ch * 576 + idx];
        aff_s[idx] = s * AFF_SCALE;
    }
    __syncthreads();
    // softmax over the 9 taps
    if (tid < 64) {
        float m = -1e30f;
#pragma unroll
        for (int k = 0; k < 9; k++) m = fmaxf(m, aff_s[tid * 9 + k]);
        float e[9], ssum = 0.f;
#pragma unroll
        for (int k = 0; k < 9; k++) { e[k] = __expf(aff_s[tid * 9 + k] - m); ssum += e[k]; }
        float inv = 1.f / ssum;
#pragma unroll
        for (int k = 0; k < 9; k++) aff_s[tid * 9 + k] = e[k] * inv;
    }
    __syncthreads();

    // store aff + affsum
    size_t abase = ((size_t)b * N_ + n) * 576;
    for (int idx = tid; idx < 576; idx += 384) g_aff[abase + idx] = aff_s[idx];
    if (tid < 9) {
        float s = 0.f;
        for (int p = 0; p < 64; p++) s += aff_s[p * 9 + tid];
        g_affsum[((size_t)b * N_ + n) * 9 + tid] = s;
    }

    // sft_site[c][k] = sum_p pix[c][p] * aff[p][k]
    {
        int c = tid;
        float acc[9];
#pragma unroll
        for (int k = 0; k < 9; k++) acc[k] = 0.f;
        for (int p = 0; p < 64; p++) {
            float pv = pix[c * 65 + p];
#pragma unroll
            for (int k = 0; k < 9; k++) acc[k] += pv * aff_s[p * 9 + k];
        }
        size_t sbase = ((size_t)b * N_ + n) * 9;
#pragma unroll
        for (int k = 0; k < 9; k++)
            g_sft_site[(sbase + k) * C_ + c] = acc[k];
    }
}

// ------------------------- 3) fold3 gather + normalize ---------------------
__global__ void gather_kernel() {
    int n = blockIdx.x, b = blockIdx.y;
    int y = n / HH_, x = n % HH_;
    int c = threadIdx.x;
    float acc = 0.f, asum = 0.f;
#pragma unroll
    for (int k = 0; k < 9; k++) {
        int i = k / 3, j = k % 3;
        int sy = y + 1 - i, sx = x + 1 - j;
        if (sy >= 0 && sy < HH_ && sx >= 0 && sx < HH_) {
            size_t sb = ((size_t)b * N_ + sy * HH_ + sx) * 9 + k;
            acc += g_sft_site[sb * C_ + c];
            asum += g_affsum[sb];
        }
    }
    g_sftn[((size_t)b * N_ + n) * C_ + c] = acc / (asum + 1e-12f);
}

// ------------------------- 4/6) tiled SGEMM --------------------------------
// A: (R1, 384) row-major.  X: (B, 784, 384).
// TRANS_OUT=false: X=g_sftn, out=g_qkv   as (B, R1, 784)
// TRANS_OUT=true : X=g_attno, out=g_projo as (B, 784, R1), + bias
template <bool TRANS_OUT>
__global__ void gemm_kernel(const float* __restrict__ A,
                            const float* __restrict__ bias, int R1) {
    __shared__ float A_s[64 * 68];
    __shared__ float X_s[64 * 68];
    int b = blockIdx.z;
    int obase = blockIdx.y * 64;
    int nbase = blockIdx.x * 64;
    int tid = threadIdx.x;
    const float* X = (TRANS_OUT ? g_attno : g_sftn) + (size_t)b * N_ * C_;
    float* outp = TRANS_OUT ? g_projo : g_qkv;

    float acc[4][4];
#pragma unroll
    for (int i = 0; i < 4; i++)
#pragma unroll
        for (int j = 0; j < 4; j++) acc[i][j] = 0.f;

    int t1 = TRANS_OUT ? (tid & 15) : (tid >> 4);  // A-row lane index
    int t2 = TRANS_OUT ? (tid >> 4) : (tid & 15);  // X-row lane index

    for (int kt = 0; kt < C_; kt += 64) {
#pragma unroll
        for (int it = 0; it < 4; it++) {
            int idx = tid + it * 256;
            int row = idx >> 4, cq = (idx & 15) << 2;
            float4 av = *(const float4*)(A + (size_t)(obase + row) * C_ + kt + cq);
            *(float4*)&A_s[row * 68 + cq] = av;
            int nrow = nbase + row;
            float4 xv = make_float4(0.f, 0.f, 0.f, 0.f);
            if (nrow < N_) xv = *(const float4*)(X + (size_t)nrow * C_ + kt + cq);
            *(float4*)&X_s[row * 68 + cq] = xv;
        }
        __syncthreads();
#pragma unroll 8
        for (int kk = 0; kk < 64; kk++) {
            float a[4], xr[4];
#pragma unroll
            for (int i = 0; i < 4; i++) a[i] = A_s[(t1 + 16 * i) * 68 + kk];
#pragma unroll
            for (int j = 0; j < 4; j++) xr[j] = X_s[(t2 + 16 * j) * 68 + kk];
#pragma unroll
            for (int i = 0; i < 4; i++)
#pragma unroll
                for (int j = 0; j < 4; j++) acc[i][j] += a[i] * xr[j];
        }
        __syncthreads();
    }

    if (!TRANS_OUT) {
#pragma unroll
        for (int i = 0; i < 4; i++) {
            int o = obase + t1 + 16 * i;
#pragma unroll
            for (int j = 0; j < 4; j++) {
                int nn = nbase + t2 + 16 * j;
                if (nn < N_) outp[((size_t)b * R1 + o) * N_ + nn] = acc[i][j];
            }
        }
    } else {
#pragma unroll
        for (int j = 0; j < 4; j++) {
            int nn = nbase + t2 + 16 * j;
            if (nn < N_) {
#pragma unroll
                for (int i = 0; i < 4; i++) {
                    int o = obase + t1 + 16 * i;
                    outp[((size_t)b * N_ + nn) * R1 + o] = acc[i][j] + bias[o];
                }
            }
        }
    }
}

// ------------------------- 5) flash attention (softmax over keys) ----------
#define FLASH_SMEM_FLOATS (3 * 3072 + 4096 + 1024 + 192)
__global__ void flash_kernel() {
    extern __shared__ float sm[];
    float* Qs   = sm;            // [d*64+m]
    float* Ks   = Qs + 3072;     // [d*64+k]
    float* Vs   = Ks + 3072;     // [d*64+k]
    float* Ps   = Vs + 3072;     // [k*64+m]
    float* red  = Ps + 4096;     // [tk*64+m]
    float* mrun = red + 1024;    // 64
    float* lrun = mrun + 64;     // 64
    float* fact = lrun + 64;     // 64

    int mbase = blockIdx.x * 64, h = blockIdx.y, b = blockIdx.z;
    int tid = threadIdx.x;
    int tk = tid >> 4, tm = tid & 15;
    const float* qkb = g_qkv + ((size_t)b * (3 * C_) + (size_t)h * (3 * HD)) * N_;

    for (int idx = tid; idx < HD * 64; idx += 256) {
        int d = idx >> 6, m = idx & 63;
        int mg = mbase + m;
        Qs[idx] = (mg < N_) ? qkb[(size_t)d * N_ + mg] : 0.f;
    }
    if (tid < 64) { mrun[tid] = -1e30f; lrun[tid] = 0.f; }
    float acc[3][4];
#pragma unroll
    for (int i = 0; i < 3; i++)
#pragma unroll
        for (int j = 0; j < 4; j++) acc[i][j] = 0.f;
    __syncthreads();

    for (int t = 0; t < 13; t++) {
        int kb = t * 64;
        for (int idx = tid; idx < HD * 64; idx += 256) {
            int d = idx >> 6, kkk = idx & 63;
            int kg = kb + kkk;
            float kv = 0.f, vv = 0.f;
            if (kg < N_) {
                kv = qkb[(size_t)(HD + d) * N_ + kg];
                vv = qkb[(size_t)(2 * HD + d) * N_ + kg];
            }
            Ks[idx] = kv;
            Vs[idx] = vv;
        }
        __syncthreads();

        // S[k][m] = scale * sum_d K[d][k]*Q[d][m]
        float sacc[4][4];
#pragma unroll
        for (int a = 0; a < 4; a++)
#pragma unroll
            for (int j = 0; j < 4; j++) sacc[a][j] = 0.f;
#pragma unroll 4
        for (int d = 0; d < HD; d++) {
            float4 kv = *(const float4*)&Ks[d * 64 + tk * 4];
            float4 qv = *(const float4*)&Qs[d * 64 + tm * 4];
            sacc[0][0] += kv.x * qv.x; sacc[0][1] += kv.x * qv.y; sacc[0][2] += kv.x * qv.z; sacc[0][3] += kv.x * qv.w;
            sacc[1][0] += kv.y * qv.x; sacc[1][1] += kv.y * qv.y; sacc[1][2] += kv.y * qv.z; sacc[1][3] += kv.y * qv.w;
            sacc[2][0] += kv.z * qv.x; sacc[2][1] += kv.z * qv.y; sacc[2][2] += kv.z * qv.z; sacc[2][3] += kv.z * qv.w;
            sacc[3][0] += kv.w * qv.x; sacc[3][1] += kv.w * qv.y; sacc[3][2] += kv.w * qv.z; sacc[3][3] += kv.w * qv.w;
        }
#pragma unroll
        for (int a = 0; a < 4; a++)
#pragma unroll
            for (int j = 0; j < 4; j++) sacc[a][j] *= ATTN_SCALE;

        // per-column (query) running max
        float pm[4];
#pragma unroll
        for (int j = 0; j < 4; j++) pm[j] = -1e30f;
#pragma unroll
        for (int a = 0; a < 4; a++) {
            bool valid = (kb + tk * 4 + a) < N_;
#pragma unroll
            for (int j = 0; j < 4; j++)
                if (valid) pm[j] = fmaxf(pm[j], sacc[a][j]);
        }
#pragma unroll
        for (int j = 0; j < 4; j++) red[tk * 64 + tm * 4 + j] = pm[j];
        __syncthreads();
        if (tid < 64) {
            float tmax = -1e30f;
#pragma unroll
            for (int i = 0; i < 16; i++) tmax = fmaxf(tmax, red[i * 64 + tid]);
            float mo = mrun[tid], mn = fmaxf(mo, tmax);
            fact[tid] = __expf(mo - mn);
            mrun[tid] = mn;
        }
        __syncthreads();

        // P = exp(S - mnew), column partial sums
        float ps[4];
#pragma unroll
        for (int j = 0; j < 4; j++) {
            float mn = mrun[tm * 4 + j];
            ps[j] = 0.f;
#pragma unroll
            for (int a = 0; a < 4; a++) {
                float p = ((kb + tk * 4 + a) < N_) ? __expf(sacc[a][j] - mn) : 0.f;
                Ps[(tk * 4 + a) * 64 + tm * 4 + j] = p;
                ps[j] += p;
            }
            red[tk * 64 + tm * 4 + j] = ps[j];
        }
        __syncthreads();
        if (tid < 64) {
            float s = 0.f;
#pragma unroll
            for (int i = 0; i < 16; i++) s += red[i * 64 + tid];
            lrun[tid] = lrun[tid] * fact[tid] + s;
        }

        // O update: acc[d][m] = acc*factor + V @ P
        float f[4];
#pragma unroll
        for (int j = 0; j < 4; j++) f[j] = fact[tm * 4 + j];
#pragma unroll
        for (int i = 0; i < 3; i++)
#pragma unroll
            for (int j = 0; j < 4; j++) acc[i][j] *= f[j];
#pragma unroll 4
        for (int kk = 0; kk < 64; kk++) {
            float v0 = Vs[(tk * 3 + 0) * 64 + kk];
            float v1 = Vs[(tk * 3 + 1) * 64 + kk];
            float v2 = Vs[(tk * 3 + 2) * 64 + kk];
            float4 p4 = *(const float4*)&Ps[kk * 64 + tm * 4];
            acc[0][0] += v0 * p4.x; acc[0][1] += v0 * p4.y; acc[0][2] += v0 * p4.z; acc[0][3] += v0 * p4.w;
            acc[1][0] += v1 * p4.x; acc[1][1] += v1 * p4.y; acc[1][2] += v1 * p4.z; acc[1][3] += v1 * p4.w;
            acc[2][0] += v2 * p4.x; acc[2][1] += v2 * p4.y; acc[2][2] += v2 * p4.z; acc[2][3] += v2 * p4.w;
        }
        __syncthreads();
    }

    // normalize + stage + coalesced write
#pragma unroll
    for (int j = 0; j < 4; j++) {
        int m = tm * 4 + j;
        float inv = 1.f / lrun[m];
#pragma unroll
        for (int i = 0; i < 3; i++) Ps[m * HD + tk * 3 + i] = acc[i][j] * inv;
    }
    __syncthreads();
    for (int idx = tid; idx < 64 * HD; idx += 256) {
        int m = idx / HD, d = idx % HD;
        int mg = mbase + m;
        if (mg < N_) g_attno[((size_t)b * N_ + mg) * C_ + h * HD + d] = Ps[idx];
    }
}

// ------------------------- 7) scatter stokens back to pixels ---------------
__global__ void scatter_kernel(float* __restrict__ out) {
    __shared__ float out9[C_ * 9];   // [c*9+k]
    __shared__ float aff_s[64 * 9];  // [p*9+k]
    int n = blockIdx.x, b = blockIdx.y;
    int y = n / HH_, x = n % HH_;
    int tid = threadIdx.x;

#pragma unroll
    for (int k = 0; k < 9; k++) {
        int yy = y + k / 3 - 1, xx = x + k % 3 - 1;
        float v = 0.f;
        if (yy >= 0 && yy < HH_ && xx >= 0 && xx < HH_)
            v = g_projo[((size_t)b * N_ + yy * HH_ + xx) * C_ + tid];
        out9[tid * 9 + k] = v;
    }
    size_t abase = ((size_t)b * N_ + n) * 576;
    for (int idx = tid; idx < 576; idx += 384) aff_s[idx] = g_aff[abase + idx];
    __syncthreads();

    int p = tid & 63, cg = tid >> 6;  // 64 pixels x 6 channel groups
    float av[9];
#pragma unroll
    for (int k = 0; k < 9; k++) av[k] = aff_s[p * 9 + k];
    int py = p >> 3, px = p & 7;
    float* obase = out + ((size_t)b * C_ * H_ + (size_t)(y * 8 + py)) * H_ + (size_t)x * 8 + px;
    for (int c = cg; c < C_; c += 6) {
        float a = 0.f;
#pragma unroll
        for (int k = 0; k < 9; k++) a += out9[c * 9 + k] * av[k];
        obase[(size_t)c * H_ * H_] = a;
    }
}

// ------------------------- launch ------------------------------------------
extern "C" void kernel_launch(void* const* d_in, const int* in_sizes, int n_in,
                              void* d_out, int out_size) {
    const float* xs     = (const float*)d_in[0];
    const float* qkv_w  = (const float*)d_in[2];
    const float* proj_w = (const float*)d_in[3];
    const float* proj_b = (const float*)d_in[4];
    float* out = (float*)d_out;

    cudaFuncSetAttribute(site_kernel, cudaFuncAttributeMaxDynamicSharedMemorySize,
                         SITE_SMEM_FLOATS * (int)sizeof(float));
    cudaFuncSetAttribute(flash_kernel, cudaFuncAttributeMaxDynamicSharedMemorySize,
                         FLASH_SMEM_FLOATS * (int)sizeof(float));

    pool_kernel<<<dim3(HH_, C_, B_), 224>>>(xs);
    site_kernel<<<dim3(N_, B_), 384, SITE_SMEM_FLOATS * sizeof(float)>>>(xs);
    gather_kernel<<<dim3(N_, B_), C_>>>();
    gemm_kernel<false><<<dim3(13, 18, B_), 256>>>(qkv_w, nullptr, 3 * C_);
    flash_kernel<<<dim3(13, HEADS, B_), 256, FLASH_SMEM_FLOATS * sizeof(float)>>>();
    gemm_kernel<true><<<dim3(13, 6, B_), 256>>>(proj_w, proj_b, C_);
    scatter_kernel<<<dim3(N_, B_), 384>>>(out);
}

// round 2
// speedup vs baseline: 1.0036x; 1.0036x over previous
#include <cuda_runtime.h>
#include <math.h>
#include <stdint.h>

#define B_    4
#define C_    384
#define H_    224
#define HH_   28
#define N_    784
#define HEADS 8
#define HD    48

#define AFF_SCALE  0.05103103630798288f   /* 384^-0.5 */
#define ATTN_SCALE 0.14433756729740643f   /* 48^-0.5 */

typedef unsigned long long ull;

__device__ __forceinline__ ull pk2(float a, float b) {
    ull r;
    asm("mov.b64 %0, {%1, %2};" : "=l"(r) : "f"(a), "f"(b));
    return r;
}
__device__ __forceinline__ void upk2(ull v, float& a, float& b) {
    asm("mov.b64 {%0, %1}, %2;" : "=f"(a), "=f"(b) : "l"(v));
}
#define FMA2(d, a, b) asm("fma.rn.f32x2 %0, %1, %2, %0;" : "+l"(d) : "l"(a), "l"(b))
#define MUL2(d, a, b) asm("mul.rn.f32x2 %0, %1, %2;" : "=l"(d) : "l"(a), "l"(b))

// ------------------------- scratch (device globals, no allocs) -------------
__device__ float g_sf[B_ * N_ * C_];              // (B, site, C)
__device__ float g_aff[B_ * N_ * 64 * 9];         // (B, n, p, k)
__device__ float g_affsum[B_ * N_ * 9];           // (B, n, k)
__device__ float g_sft_site[B_ * N_ * 9 * C_];    // (B, n, k, C)
__device__ float g_sftn[B_ * N_ * C_];            // (B, n, C)
__device__ float g_qkv[B_ * 3 * C_ * N_];         // (B, o, n)
__device__ float g_attno[B_ * N_ * C_];           // (B, n, C)
__device__ float g_projo[B_ * N_ * C_];           // (B, n, C)

// ------------------------- 1) 8x8 average pool -----------------------------
__global__ void pool_kernel(const float* __restrict__ xs) {
    int y = blockIdx.x, c = blockIdx.y, b = blockIdx.z;
    int t = threadIdx.x;  // 0..223
    const float* base = xs + ((size_t)(b * C_ + c) * H_ + (size_t)y * 8) * H_;
    float s = 0.f;
#pragma unroll
    for (int dy = 0; dy < 8; dy++) s += base[dy * H_ + t];
    __shared__ float sm[224];
    sm[t] = s;
    __syncthreads();
    if (t < HH_) {
        float acc = 0.f;
#pragma unroll
        for (int i = 0; i < 8; i++) acc += sm[t * 8 + i];
        g_sf[((size_t)b * N_ + (size_t)y * HH_ + t) * C_ + c] = acc * (1.0f / 64.0f);
    }
}

// ------------------------- 2) per-site affinity + aggregation --------------
// smem: pix[c*65+p] + sf9[c*10+k] + lpart[chunk*576+p*9+k] + aff[p*10+k]
#define SITE_SMEM_FLOATS (C_ * 65 + C_ * 10 + 6 * 576 + 640)
__global__ void site_kernel(const float* __restrict__ xs) {
    extern __shared__ __align__(16) float sm[];
    float* pix   = sm;                 // [c*65 + p]
    float* sf9   = pix + C_ * 65;      // [c*10 + k]  (pad 10 for u64 pair loads)
    float* lpart = sf9 + C_ * 10;      // [chunk*576 + p*9 + k]
    float* aff_s = lpart + 6 * 576;    // [p*10 + k]

    int n = blockIdx.x, b = blockIdx.y;
    int y = n / HH_, x = n % HH_;
    int tid = threadIdx.x;

    const float* xbase = xs + ((size_t)b * C_ * H_ + (size_t)y * 8) * H_ + (size_t)x * 8;
    for (int q = tid; q < C_ * 16; q += 384) {
        int c = q >> 4, r = q & 15;
        int py = r >> 1, pxq = (r & 1) << 2;
        float4 v = *(const float4*)(xbase + ((size_t)c * H_ + py) * H_ + pxq);
        int p = py * 8 + pxq;
        pix[c * 65 + p + 0] = v.x;
        pix[c * 65 + p + 1] = v.y;
        pix[c * 65 + p + 2] = v.z;
        pix[c * 65 + p + 3] = v.w;
    }
#pragma unroll
    for (int k = 0; k < 9; k++) {
        int yy = y + k / 3 - 1, xx = x + k % 3 - 1;
        float v = 0.f;
        if (yy >= 0 && yy < HH_ && xx >= 0 && xx < HH_)
            v = g_sf[((size_t)b * N_ + yy * HH_ + xx) * C_ + tid];
        sf9[tid * 10 + k] = v;
    }
    __syncthreads();

    // logits: 6 chunks of 64 channels, paired FMA over taps
    {
        int p = tid & 63, chunk = tid >> 6;
        ull acc2[4] = {0, 0, 0, 0};
        float acc8 = 0.f;
        for (int cc = 0; cc < 64; cc++) {
            int c = (chunk << 6) + cc;
            float pv = pix[c * 65 + p];
            ull pp = pk2(pv, pv);
            const float* s9 = &sf9[c * 10];
            ull s01 = *(const ull*)(s9 + 0);
            ull s23 = *(const ull*)(s9 + 2);
            ull s45 = *(const ull*)(s9 + 4);
            ull s67 = *(const ull*)(s9 + 6);
            FMA2(acc2[0], pp, s01);
            FMA2(acc2[1], pp, s23);
            FMA2(acc2[2], pp, s45);
            FMA2(acc2[3], pp, s67);
            acc8 = fmaf(pv, s9[8], acc8);
        }
        float l[9];
        upk2(acc2[0], l[0], l[1]);
        upk2(acc2[1], l[2], l[3]);
        upk2(acc2[2], l[4], l[5]);
        upk2(acc2[3], l[6], l[7]);
        l[8] = acc8;
#pragma unroll
        for (int k = 0; k < 9; k++) lpart[chunk * 576 + p * 9 + k] = l[k];
    }
    __syncthreads();
    for (int idx = tid; idx < 576; idx += 384) {
        float s = 0.f;
#pragma unroll
        for (int ch = 0; ch < 6; ch++) s += lpart[ch * 576 + idx];
        int p = idx / 9, k = idx - p * 9;
        aff_s[p * 10 + k] = s * AFF_SCALE;
    }
    __syncthreads();
    if (tid < 64) {
        float m = -1e30f;
#pragma unroll
        for (int k = 0; k < 9; k++) m = fmaxf(m, aff_s[tid * 10 + k]);
        float e[9], ssum = 0.f;
#pragma unroll
        for (int k = 0; k < 9; k++) { e[k] = __expf(aff_s[tid * 10 + k] - m); ssum += e[k]; }
        float inv = 1.f / ssum;
#pragma unroll
        for (int k = 0; k < 9; k++) aff_s[tid * 10 + k] = e[k] * inv;
    }
    __syncthreads();

    size_t abase = ((size_t)b * N_ + n) * 576;
    for (int idx = tid; idx < 576; idx += 384) {
        int p = idx / 9, k = idx - p * 9;
        g_aff[abase + idx] = aff_s[p * 10 + k];
    }
    if (tid < 9) {
        float s = 0.f;
        for (int p = 0; p < 64; p++) s += aff_s[p * 10 + tid];
        g_affsum[((size_t)b * N_ + n) * 9 + tid] = s;
    }

    // sft_site[c][k] = sum_p pix[c][p] * aff[p][k]
    {
        int c = tid;
        ull acc2[4] = {0, 0, 0, 0};
        float acc8 = 0.f;
        for (int p = 0; p < 64; p++) {
            float pv = pix[c * 65 + p];
            ull pp = pk2(pv, pv);
            const float* a9 = &aff_s[p * 10];
            ull a01 = *(const ull*)(a9 + 0);
            ull a23 = *(const ull*)(a9 + 2);
            ull a45 = *(const ull*)(a9 + 4);
            ull a67 = *(const ull*)(a9 + 6);
            FMA2(acc2[0], pp, a01);
            FMA2(acc2[1], pp, a23);
            FMA2(acc2[2], pp, a45);
            FMA2(acc2[3], pp, a67);
            acc8 = fmaf(pv, a9[8], acc8);
        }
        float r[9];
        upk2(acc2[0], r[0], r[1]);
        upk2(acc2[1], r[2], r[3]);
        upk2(acc2[2], r[4], r[5]);
        upk2(acc2[3], r[6], r[7]);
        r[8] = acc8;
        size_t sbase = ((size_t)b * N_ + n) * 9;
#pragma unroll
        for (int k = 0; k < 9; k++)
            g_sft_site[(sbase + k) * C_ + c] = r[k];
    }
}

// ------------------------- 3) fold3 gather + normalize ---------------------
__global__ void gather_kernel() {
    int n = blockIdx.x, b = blockIdx.y;
    int y = n / HH_, x = n % HH_;
    int c = threadIdx.x;
    float acc = 0.f, asum = 0.f;
#pragma unroll
    for (int k = 0; k < 9; k++) {
        int i = k / 3, j = k % 3;
        int sy = y + 1 - i, sx = x + 1 - j;
        if (sy >= 0 && sy < HH_ && sx >= 0 && sx < HH_) {
            size_t sb = ((size_t)b * N_ + sy * HH_ + sx) * 9 + k;
            acc += g_sft_site[sb * C_ + c];
            asum += g_affsum[sb];
        }
    }
    g_sftn[((size_t)b * N_ + n) * C_ + c] = acc / (asum + 1e-12f);
}

// ------------------------- 4/6) FFMA2 SGEMM, 128x128 tile ------------------
// A: (R1, 384) row-major.  X: (B, 784, 384).
// TRANS_OUT=false: X=g_sftn, out=g_qkv   as (B, R1, 784)
// TRANS_OUT=true : X=g_attno, out=g_projo as (B, 784, R1), + bias
template <bool TRANS_OUT>
__global__ __launch_bounds__(256, 2) void gemm_kernel(const float* __restrict__ A,
                                                      const float* __restrict__ bias,
                                                      int R1) {
    __shared__ __align__(16) ull   A_s[16 * 132];  // [kk*132+m], value duplicated {a,a}
    __shared__ __align__(16) float X_s[16 * 196];  // [kk*196 + (n>>3)*12 + (n&7)]
    int b = blockIdx.z;
    int obase = blockIdx.y * 128;
    int nbase = blockIdx.x * 128;
    int tid = threadIdx.x;
    int tm = tid >> 4, tn = tid & 15;
    const float* X = (TRANS_OUT ? g_attno : g_sftn) + (size_t)b * N_ * C_;
    float* outp = TRANS_OUT ? g_projo : g_qkv;

    ull acc[8][4];
#pragma unroll
    for (int i = 0; i < 8; i++)
#pragma unroll
        for (int j = 0; j < 4; j++) acc[i][j] = 0ull;

    for (int kt = 0; kt < C_; kt += 16) {
#pragma unroll
        for (int it = 0; it < 2; it++) {
            int idx = tid + it * 256;
            int m = idx >> 2, kq = (idx & 3) << 2;
            float4 v = *(const float4*)(A + (size_t)(obase + m) * C_ + kt + kq);
            A_s[(kq + 0) * 132 + m] = pk2(v.x, v.x);
            A_s[(kq + 1) * 132 + m] = pk2(v.y, v.y);
            A_s[(kq + 2) * 132 + m] = pk2(v.z, v.z);
            A_s[(kq + 3) * 132 + m] = pk2(v.w, v.w);
        }
#pragma unroll
        for (int it = 0; it < 2; it++) {
            int idx = tid + it * 256;
            int n = idx >> 2, kq = (idx & 3) << 2;
            float4 v = make_float4(0.f, 0.f, 0.f, 0.f);
            if (nbase + n < N_) v = *(const float4*)(X + (size_t)(nbase + n) * C_ + kt + kq);
            int xb = (n >> 3) * 12 + (n & 7);
            X_s[(kq + 0) * 196 + xb] = v.x;
            X_s[(kq + 1) * 196 + xb] = v.y;
            X_s[(kq + 2) * 196 + xb] = v.z;
            X_s[(kq + 3) * 196 + xb] = v.w;
        }
        __syncthreads();
#pragma unroll
        for (int kk = 0; kk < 16; kk++) {
            ull a[8];
#pragma unroll
            for (int i = 0; i < 8; i++) a[i] = A_s[kk * 132 + tm * 8 + i];
            ulonglong2 x01 = *(const ulonglong2*)&X_s[kk * 196 + tn * 12];
            ulonglong2 x23 = *(const ulonglong2*)&X_s[kk * 196 + tn * 12 + 4];
#pragma unroll
            for (int i = 0; i < 8; i++) {
                FMA2(acc[i][0], a[i], x01.x);
                FMA2(acc[i][1], a[i], x01.y);
                FMA2(acc[i][2], a[i], x23.x);
                FMA2(acc[i][3], a[i], x23.y);
            }
        }
        __syncthreads();
    }

    int n0 = nbase + tn * 8;
    if (!TRANS_OUT) {
        if (n0 < N_) {
#pragma unroll
            for (int i = 0; i < 8; i++) {
                int o = obase + tm * 8 + i;
                float f[8];
                upk2(acc[i][0], f[0], f[1]);
                upk2(acc[i][1], f[2], f[3]);
                upk2(acc[i][2], f[4], f[5]);
                upk2(acc[i][3], f[6], f[7]);
                float* dst = outp + ((size_t)b * R1 + o) * N_ + n0;
                *(float4*)(dst)     = make_float4(f[0], f[1], f[2], f[3]);
                *(float4*)(dst + 4) = make_float4(f[4], f[5], f[6], f[7]);
            }
        }
    } else {
        if (n0 < N_) {
            float4 bv0 = *(const float4*)(bias + obase + tm * 8);
            float4 bv1 = *(const float4*)(bias + obase + tm * 8 + 4);
#pragma unroll
            for (int jp = 0; jp < 4; jp++) {
                float f0[8], f1[8];
#pragma unroll
                for (int i = 0; i < 8; i++) upk2(acc[i][jp], f0[i], f1[i]);
                float* d0 = outp + ((size_t)b * N_ + n0 + 2 * jp) * R1 + obase + tm * 8;
                float* d1 = d0 + R1;
                *(float4*)(d0)     = make_float4(f0[0] + bv0.x, f0[1] + bv0.y, f0[2] + bv0.z, f0[3] + bv0.w);
                *(float4*)(d0 + 4) = make_float4(f0[4] + bv1.x, f0[5] + bv1.y, f0[6] + bv1.z, f0[7] + bv1.w);
                *(float4*)(d1)     = make_float4(f1[0] + bv0.x, f1[1] + bv0.y, f1[2] + bv0.z, f1[3] + bv0.w);
                *(float4*)(d1 + 4) = make_float4(f1[4] + bv1.x, f1[5] + bv1.y, f1[6] + bv1.z, f1[7] + bv1.w);
            }
        }
    }
}

// ------------------------- 5) flash attention (softmax over keys) ----------
#define FLASH_SMEM_FLOATS (3 * 3072 + 4096 + 1024 + 192)
__global__ void flash_kernel() {
    extern __shared__ __align__(16) float fsm[];
    float* Qs   = fsm;           // [d*64+m]
    float* Ks   = Qs + 3072;     // [d*64+k]
    float* Vs   = Ks + 3072;     // [d*64+k]
    float* Ps   = Vs + 3072;     // [k*64+m]
    float* red  = Ps + 4096;     // [tk*64+m]
    float* mrun = red + 1024;    // 64
    float* lrun = mrun + 64;     // 64
    float* fact = lrun + 64;     // 64

    int mbase = blockIdx.x * 64, h = blockIdx.y, b = blockIdx.z;
    int tid = threadIdx.x;
    int tk = tid >> 4, tm = tid & 15;
    const float* qkb = g_qkv + ((size_t)b * (3 * C_) + (size_t)h * (3 * HD)) * N_;

    for (int idx = tid; idx < HD * 64; idx += 256) {
        int d = idx >> 6, m = idx & 63;
        int mg = mbase + m;
        Qs[idx] = (mg < N_) ? qkb[(size_t)d * N_ + mg] : 0.f;
    }
    if (tid < 64) { mrun[tid] = -1e30f; lrun[tid] = 0.f; }
    ull o2[3][2];
#pragma unroll
    for (int i = 0; i < 3; i++) { o2[i][0] = 0ull; o2[i][1] = 0ull; }
    __syncthreads();

    for (int t = 0; t < 13; t++) {
        int kb = t * 64;
        for (int idx = tid; idx < HD * 64; idx += 256) {
            int d = idx >> 6, kkk = idx & 63;
            int kg = kb + kkk;
            float kv = 0.f, vv = 0.f;
            if (kg < N_) {
                kv = qkb[(size_t)(HD + d) * N_ + kg];
                vv = qkb[(size_t)(2 * HD + d) * N_ + kg];
            }
            Ks[idx] = kv;
            Vs[idx] = vv;
        }
        __syncthreads();

        // S[k][m] via FFMA2 (pairs along m)
        ull s2[4][2];
#pragma unroll
        for (int a = 0; a < 4; a++) { s2[a][0] = 0ull; s2[a][1] = 0ull; }
#pragma unroll 4
        for (int d = 0; d < HD; d++) {
            float4 kv = *(const float4*)&Ks[d * 64 + tk * 4];
            ulonglong2 q2 = *(const ulonglong2*)&Qs[d * 64 + tm * 4];
            ull k0 = pk2(kv.x, kv.x), k1 = pk2(kv.y, kv.y);
            ull k2 = pk2(kv.z, kv.z), k3 = pk2(kv.w, kv.w);
            FMA2(s2[0][0], k0, q2.x); FMA2(s2[0][1], k0, q2.y);
            FMA2(s2[1][0], k1, q2.x); FMA2(s2[1][1], k1, q2.y);
            FMA2(s2[2][0], k2, q2.x); FMA2(s2[2][1], k2, q2.y);
            FMA2(s2[3][0], k3, q2.x); FMA2(s2[3][1], k3, q2.y);
        }
        float sacc[4][4];
#pragma unroll
        for (int a = 0; a < 4; a++) {
            upk2(s2[a][0], sacc[a][0], sacc[a][1]);
            upk2(s2[a][1], sacc[a][2], sacc[a][3]);
#pragma unroll
            for (int j = 0; j < 4; j++) sacc[a][j] *= ATTN_SCALE;
        }

        float pm[4];
#pragma unroll
        for (int j = 0; j < 4; j++) pm[j] = -1e30f;
#pragma unroll
        for (int a = 0; a < 4; a++) {
            bool valid = (kb + tk * 4 + a) < N_;
#pragma unroll
            for (int j = 0; j < 4; j++)
                if (valid) pm[j] = fmaxf(pm[j], sacc[a][j]);
        }
#pragma unroll
        for (int j = 0; j < 4; j++) red[tk * 64 + tm * 4 + j] = pm[j];
        __syncthreads();
        if (tid < 64) {
            float tmax = -1e30f;
#pragma unroll
            for (int i = 0; i < 16; i++) tmax = fmaxf(tmax, red[i * 64 + tid]);
            float mo = mrun[tid], mn = fmaxf(mo, tmax);
            fact[tid] = __expf(mo - mn);
            mrun[tid] = mn;
        }
        __syncthreads();

        float ps[4];
#pragma unroll
        for (int j = 0; j < 4; j++) {
            float mn = mrun[tm * 4 + j];
            ps[j] = 0.f;
#pragma unroll
            for (int a = 0; a < 4; a++) {
                float p = ((kb + tk * 4 + a) < N_) ? __expf(sacc[a][j] - mn) : 0.f;
                Ps[(tk * 4 + a) * 64 + tm * 4 + j] = p;
                ps[j] += p;
            }
            red[tk * 64 + tm * 4 + j] = ps[j];
        }
        __syncthreads();
        if (tid < 64) {
            float s = 0.f;
#pragma unroll
            for (int i = 0; i < 16; i++) s += red[i * 64 + tid];
            lrun[tid] = lrun[tid] * fact[tid] + s;
        }

        // O update via FFMA2
        ull f2[2];
        f2[0] = pk2(fact[tm * 4 + 0], fact[tm * 4 + 1]);
        f2[1] = pk2(fact[tm * 4 + 2], fact[tm * 4 + 3]);
#pragma unroll
        for (int i = 0; i < 3; i++) {
            MUL2(o2[i][0], o2[i][0], f2[0]);
            MUL2(o2[i][1], o2[i][1], f2[1]);
        }
#pragma unroll 4
        for (int kk = 0; kk < 64; kk++) {
            float v0 = Vs[(tk * 3 + 0) * 64 + kk];
            float v1 = Vs[(tk * 3 + 1) * 64 + kk];
            float v2 = Vs[(tk * 3 + 2) * 64 + kk];
            ull pv0 = pk2(v0, v0), pv1 = pk2(v1, v1), pv2 = pk2(v2, v2);
            ulonglong2 p2 = *(const ulonglong2*)&Ps[kk * 64 + tm * 4];
            FMA2(o2[0][0], pv0, p2.x); FMA2(o2[0][1], pv0, p2.y);
            FMA2(o2[1][0], pv1, p2.x); FMA2(o2[1][1], pv1, p2.y);
            FMA2(o2[2][0], pv2, p2.x); FMA2(o2[2][1], pv2, p2.y);
        }
        __syncthreads();
    }

    float acc[3][4];
#pragma unroll
    for (int i = 0; i < 3; i++) {
        upk2(o2[i][0], acc[i][0], acc[i][1]);
        upk2(o2[i][1], acc[i][2], acc[i][3]);
    }
#pragma unroll
    for (int j = 0; j < 4; j++) {
        int m = tm * 4 + j;
        float inv = 1.f / lrun[m];
#pragma unroll
        for (int i = 0; i < 3; i++) Ps[m * HD + tk * 3 + i] = acc[i][j] * inv;
    }
    __syncthreads();
    for (int idx = tid; idx < 64 * HD; idx += 256) {
        int m = idx / HD, d = idx % HD;
        int mg = mbase + m;
        if (mg < N_) g_attno[((size_t)b * N_ + mg) * C_ + h * HD + d] = Ps[idx];
    }
}

// ------------------------- 7) scatter stokens back to pixels ---------------
__global__ void scatter_kernel(float* __restrict__ out) {
    __shared__ __align__(16) float out9[C_ * 10];  // [c*10+k]
    __shared__ float aff_s[64 * 9];                // [p*9+k]
    int n = blockIdx.x, b = blockIdx.y;
    int y = n / HH_, x = n % HH_;
    int tid = threadIdx.x;

#pragma unroll
    for (int k = 0; k < 9; k++) {
        int yy = y + k / 3 - 1, xx = x + k % 3 - 1;
        float v = 0.f;
        if (yy >= 0 && yy < HH_ && xx >= 0 && xx < HH_)
            v = g_projo[((size_t)b * N_ + yy * HH_ + xx) * C_ + tid];
        out9[tid * 10 + k] = v;
    }
    size_t abase = ((size_t)b * N_ + n) * 576;
    for (int idx = tid; idx < 576; idx += 384) aff_s[idx] = g_aff[abase + idx];
    __syncthreads();

    int p = tid & 63, cg = tid >> 6;  // 64 pixels x 6 channel groups
    float av[9];
#pragma unroll
    for (int k = 0; k < 9; k++) av[k] = aff_s[p * 9 + k];
    ull av2[4];
    av2[0] = pk2(av[0], av[1]);
    av2[1] = pk2(av[2], av[3]);
    av2[2] = pk2(av[4], av[5]);
    av2[3] = pk2(av[6], av[7]);
    int py = p >> 3, px = p & 7;
    float* obase = out + ((size_t)b * C_ * H_ + (size_t)(y * 8 + py)) * H_ + (size_t)x * 8 + px;
    for (int c = cg; c < C_; c += 6) {
        const float* o9 = &out9[c * 10];
        ull o01 = *(const ull*)(o9 + 0);
        ull o23 = *(const ull*)(o9 + 2);
        ull o45 = *(const ull*)(o9 + 4);
        ull o67 = *(const ull*)(o9 + 6);
        ull acc2 = 0ull;
        FMA2(acc2, av2[0], o01);
        FMA2(acc2, av2[1], o23);
        FMA2(acc2, av2[2], o45);
        FMA2(acc2, av2[3], o67);
        float lo, hi;
        upk2(acc2, lo, hi);
        obase[(size_t)c * H_ * H_] = lo + hi + av[8] * o9[8];
    }
}

// ------------------------- launch ------------------------------------------
extern "C" void kernel_launch(void* const* d_in, const int* in_sizes, int n_in,
                              void* d_out, int out_size) {
    const float* xs     = (const float*)d_in[0];
    const float* qkv_w  = (const float*)d_in[2];
    const float* proj_w = (const float*)d_in[3];
    const float* proj_b = (const float*)d_in[4];
    float* out = (float*)d_out;

    cudaFuncSetAttribute(site_kernel, cudaFuncAttributeMaxDynamicSharedMemorySize,
                         SITE_SMEM_FLOATS * (int)sizeof(float));
    cudaFuncSetAttribute(flash_kernel, cudaFuncAttributeMaxDynamicSharedMemorySize,
                         FLASH_SMEM_FLOATS * (int)sizeof(float));

    pool_kernel<<<dim3(HH_, C_, B_), 224>>>(xs);
    site_kernel<<<dim3(N_, B_), 384, SITE_SMEM_FLOATS * sizeof(float)>>>(xs);
    gather_kernel<<<dim3(N_, B_), C_>>>();
    gemm_kernel<false><<<dim3(7, 9, B_), 256>>>(qkv_w, nullptr, 3 * C_);
    flash_kernel<<<dim3(13, HEADS, B_), 256, FLASH_SMEM_FLOATS * sizeof(float)>>>();
    gemm_kernel<true><<<dim3(7, 3, B_), 256>>>(proj_w, proj_b, C_);
    scatter_kernel<<<dim3(N_, B_), 384>>>(out);
}

// round 5
// speedup vs baseline: 1.1196x; 1.1156x over previous
#include <cuda_runtime.h>
#include <cuda_bf16.h>
#include <math.h>
#include <stdint.h>

#define B_    4
#define C_    384
#define H_    224
#define HH_   28
#define N_    784
#define HEADS 8
#define HD    48

#define AFF_SCALE  0.05103103630798288f   /* 384^-0.5 */
#define ATTN_SCALE 0.14433756729740643f   /* 48^-0.5 */

typedef unsigned long long ull;

__device__ __forceinline__ ull pk2(float a, float b) {
    ull r;
    asm("mov.b64 %0, {%1, %2};" : "=l"(r) : "f"(a), "f"(b));
    return r;
}
__device__ __forceinline__ void upk2(ull v, float& a, float& b) {
    asm("mov.b64 {%0, %1}, %2;" : "=f"(a), "=f"(b) : "l"(v));
}
#define FMA2(d, a, b) asm("fma.rn.f32x2 %0, %1, %2, %0;" : "+l"(d) : "l"(a), "l"(b))
#define MUL2(d, a, b) asm("mul.rn.f32x2 %0, %1, %2;" : "=l"(d) : "l"(a), "l"(b))

__device__ __forceinline__ uint32_t smem_u32(const void* p) {
    uint32_t a;
    asm("{ .reg .u64 t; cvta.to.shared.u64 t, %1; cvt.u32.u64 %0, t; }" : "=r"(a) : "l"(p));
    return a;
}
__device__ __forceinline__ uint32_t pk_bf(__nv_bfloat16 a, __nv_bfloat16 b) {
    uint16_t ra = *(uint16_t*)&a, rb = *(uint16_t*)&b;
    return (uint32_t)ra | ((uint32_t)rb << 16);
}

#define LDSM4(r, addr) \
    asm volatile("ldmatrix.sync.aligned.m8n8.x4.shared.b16 {%0,%1,%2,%3}, [%4];" \
                 : "=r"((r)[0]), "=r"((r)[1]), "=r"((r)[2]), "=r"((r)[3]) : "r"(addr))
#define LDSM2(r, addr) \
    asm volatile("ldmatrix.sync.aligned.m8n8.x2.shared.b16 {%0,%1}, [%2];" \
                 : "=r"((r)[0]), "=r"((r)[1]) : "r"(addr))
#define MMA16816(d, a, b) \
    asm volatile("mma.sync.aligned.m16n8k16.row.col.f32.bf16.bf16.f32 " \
                 "{%0,%1,%2,%3}, {%4,%5,%6,%7}, {%8,%9}, {%0,%1,%2,%3};" \
                 : "+f"((d)[0]), "+f"((d)[1]), "+f"((d)[2]), "+f"((d)[3]) \
                 : "r"((a)[0]), "r"((a)[1]), "r"((a)[2]), "r"((a)[3]), \
                   "r"((b)[0]), "r"((b)[1]))

// ------------------------- scratch (device globals, no allocs) -------------
__device__ float g_sf[B_ * N_ * C_];              // (B, site, C)
__device__ float g_aff[B_ * N_ * 64 * 9];         // (B, n, p, k)
__device__ float g_affsum[B_ * N_ * 9];           // (B, n, k)
__device__ float g_sft_site[B_ * N_ * 9 * C_];    // (B, n, k, C)
__device__ float g_sftn[B_ * N_ * C_];            // (B, n, C)
__device__ float g_qkv[B_ * 3 * C_ * N_];         // (B, o, n)
__device__ float g_attno[B_ * N_ * C_];           // (B, n, C)
__device__ float g_projo[B_ * N_ * C_];           // (B, n, C)

// ------------------------- 1) 8x8 average pool -----------------------------
__global__ void pool_kernel(const float* __restrict__ xs) {
    int y = blockIdx.x, c = blockIdx.y, b = blockIdx.z;
    int t = threadIdx.x;  // 0..223
    const float* base = xs + ((size_t)(b * C_ + c) * H_ + (size_t)y * 8) * H_;
    float s = 0.f;
#pragma unroll
    for (int dy = 0; dy < 8; dy++) s += base[dy * H_ + t];
    __shared__ float sm[224];
    sm[t] = s;
    __syncthreads();
    if (t < HH_) {
        float acc = 0.f;
#pragma unroll
        for (int i = 0; i < 8; i++) acc += sm[t * 8 + i];
        g_sf[((size_t)b * N_ + (size_t)y * HH_ + t) * C_ + c] = acc * (1.0f / 64.0f);
    }
}

// ------------------------- 2) per-site affinity + aggregation --------------
#define SITE_SMEM_FLOATS (C_ * 65 + C_ * 10 + 6 * 576 + 640)
__global__ void site_kernel(const float* __restrict__ xs) {
    extern __shared__ __align__(16) float sm[];
    float* pix   = sm;                 // [c*65 + p]
    float* sf9   = pix + C_ * 65;      // [c*10 + k]
    float* lpart = sf9 + C_ * 10;      // [chunk*576 + p*9 + k]
    float* aff_s = lpart + 6 * 576;    // [p*10 + k]

    int n = blockIdx.x, b = blockIdx.y;
    int y = n / HH_, x = n % HH_;
    int tid = threadIdx.x;

    const float* xbase = xs + ((size_t)b * C_ * H_ + (size_t)y * 8) * H_ + (size_t)x * 8;
    for (int q = tid; q < C_ * 16; q += 384) {
        int c = q >> 4, r = q & 15;
        int py = r >> 1, pxq = (r & 1) << 2;
        float4 v = *(const float4*)(xbase + ((size_t)c * H_ + py) * H_ + pxq);
        int p = py * 8 + pxq;
        pix[c * 65 + p + 0] = v.x;
        pix[c * 65 + p + 1] = v.y;
        pix[c * 65 + p + 2] = v.z;
        pix[c * 65 + p + 3] = v.w;
    }
#pragma unroll
    for (int k = 0; k < 9; k++) {
        int yy = y + k / 3 - 1, xx = x + k % 3 - 1;
        float v = 0.f;
        if (yy >= 0 && yy < HH_ && xx >= 0 && xx < HH_)
            v = g_sf[((size_t)b * N_ + yy * HH_ + xx) * C_ + tid];
        sf9[tid * 10 + k] = v;
    }
    __syncthreads();

    {
        int p = tid & 63, chunk = tid >> 6;
        ull acc2[4] = {0, 0, 0, 0};
        float acc8 = 0.f;
        for (int cc = 0; cc < 64; cc++) {
            int c = (chunk << 6) + cc;
            float pv = pix[c * 65 + p];
            ull pp = pk2(pv, pv);
            const float* s9 = &sf9[c * 10];
            ull s01 = *(const ull*)(s9 + 0);
            ull s23 = *(const ull*)(s9 + 2);
            ull s45 = *(const ull*)(s9 + 4);
            ull s67 = *(const ull*)(s9 + 6);
            FMA2(acc2[0], pp, s01);
            FMA2(acc2[1], pp, s23);
            FMA2(acc2[2], pp, s45);
            FMA2(acc2[3], pp, s67);
            acc8 = fmaf(pv, s9[8], acc8);
        }
        float l[9];
        upk2(acc2[0], l[0], l[1]);
        upk2(acc2[1], l[2], l[3]);
        upk2(acc2[2], l[4], l[5]);
        upk2(acc2[3], l[6], l[7]);
        l[8] = acc8;
#pragma unroll
        for (int k = 0; k < 9; k++) lpart[chunk * 576 + p * 9 + k] = l[k];
    }
    __syncthreads();
    for (int idx = tid; idx < 576; idx += 384) {
        float s = 0.f;
#pragma unroll
        for (int ch = 0; ch < 6; ch++) s += lpart[ch * 576 + idx];
        int p = idx / 9, k = idx - p * 9;
        aff_s[p * 10 + k] = s * AFF_SCALE;
    }
    __syncthreads();
    if (tid < 64) {
        float m = -1e30f;
#pragma unroll
        for (int k = 0; k < 9; k++) m = fmaxf(m, aff_s[tid * 10 + k]);
        float e[9], ssum = 0.f;
#pragma unroll
        for (int k = 0; k < 9; k++) { e[k] = __expf(aff_s[tid * 10 + k] - m); ssum += e[k]; }
        float inv = 1.f / ssum;
#pragma unroll
        for (int k = 0; k < 9; k++) aff_s[tid * 10 + k] = e[k] * inv;
    }
    __syncthreads();

    size_t abase = ((size_t)b * N_ + n) * 576;
    for (int idx = tid; idx < 576; idx += 384) {
        int p = idx / 9, k = idx - p * 9;
        g_aff[abase + idx] = aff_s[p * 10 + k];
    }
    if (tid < 9) {
        float s = 0.f;
        for (int p = 0; p < 64; p++) s += aff_s[p * 10 + tid];
        g_affsum[((size_t)b * N_ + n) * 9 + tid] = s;
    }

    {
        int c = tid;
        ull acc2[4] = {0, 0, 0, 0};
        float acc8 = 0.f;
        for (int p = 0; p < 64; p++) {
            float pv = pix[c * 65 + p];
            ull pp = pk2(pv, pv);
            const float* a9 = &aff_s[p * 10];
            ull a01 = *(const ull*)(a9 + 0);
            ull a23 = *(const ull*)(a9 + 2);
            ull a45 = *(const ull*)(a9 + 4);
            ull a67 = *(const ull*)(a9 + 6);
            FMA2(acc2[0], pp, a01);
            FMA2(acc2[1], pp, a23);
            FMA2(acc2[2], pp, a45);
            FMA2(acc2[3], pp, a67);
            acc8 = fmaf(pv, a9[8], acc8);
        }
        float r[9];
        upk2(acc2[0], r[0], r[1]);
        upk2(acc2[1], r[2], r[3]);
        upk2(acc2[2], r[4], r[5]);
        upk2(acc2[3], r[6], r[7]);
        r[8] = acc8;
        size_t sbase = ((size_t)b * N_ + n) * 9;
#pragma unroll
        for (int k = 0; k < 9; k++)
            g_sft_site[(sbase + k) * C_ + c] = r[k];
    }
}

// ------------------------- 3) fold3 gather + normalize ---------------------
__global__ void gather_kernel() {
    int n = blockIdx.x, b = blockIdx.y;
    int y = n / HH_, x = n % HH_;
    int c = threadIdx.x;
    float acc = 0.f, asum = 0.f;
#pragma unroll
    for (int k = 0; k < 9; k++) {
        int i = k / 3, j = k % 3;
        int sy = y + 1 - i, sx = x + 1 - j;
        if (sy >= 0 && sy < HH_ && sx >= 0 && sx < HH_) {
            size_t sb = ((size_t)b * N_ + sy * HH_ + sx) * 9 + k;
            acc += g_sft_site[sb * C_ + c];
            asum += g_affsum[sb];
        }
    }
    g_sftn[((size_t)b * N_ + n) * C_ + c] = acc / (asum + 1e-12f);
}

// ------------------------- 4/6) mma.sync bf16-split GEMM -------------------
// D[o][n] = sum_c A[o][c]*X[n][c].  A (R1,384) row-major, X (B,784,384).
// bf16 hi/lo split: D = Ah*Xh + Ah*Xl + Al*Xh.
// Tile 128(m=o) x 128(n); 8 warps = 4(m) x 2(n); warp tile 32x64.
#define SGA 72                         /* smem stride in halves (144B) */
#define GEMM_DSMEM (4 * 128 * SGA * 2) /* 73728 B; stage 128*128*4=65536 fits */
// stage swizzle: keeps float2/float4 alignment (xor is a multiple of 4)
__device__ __forceinline__ int ssw(int m, int n) { return m * 128 + (n ^ (((m >> 2) & 7) << 2)); }

template <bool TRANS_OUT>
__global__ __launch_bounds__(256) void gemm_mma(const float* __restrict__ A,
                                                const float* __restrict__ bias,
                                                int R1) {
    extern __shared__ __align__(16) char dyn[];
    __nv_bfloat16* Ah = (__nv_bfloat16*)dyn;
    __nv_bfloat16* Al = Ah + 128 * SGA;
    __nv_bfloat16* Xh = Al + 128 * SGA;
    __nv_bfloat16* Xl = Xh + 128 * SGA;

    int b = blockIdx.z;
    int obase = blockIdx.y * 128;
    int nbase = blockIdx.x * 128;
    int tid = threadIdx.x;
    int lane = tid & 31, w = tid >> 5;
    int wm = w & 3, wn = w >> 2;
    const float* X = (TRANS_OUT ? g_attno : g_sftn) + (size_t)b * N_ * C_;

    uint32_t baAh = smem_u32(Ah), baAl = smem_u32(Al);
    uint32_t baXh = smem_u32(Xh), baXl = smem_u32(Xl);

    float acc[2][8][4];
#pragma unroll
    for (int i = 0; i < 2; i++)
#pragma unroll
        for (int j = 0; j < 8; j++)
#pragma unroll
            for (int q = 0; q < 4; q++) acc[i][j][q] = 0.f;

    for (int chunk = 0; chunk < 6; chunk++) {
        int kt = chunk * 64;
        __syncthreads();
#pragma unroll
        for (int it = 0; it < 8; it++) {
            int idx = tid + it * 256;   // 128 rows x 16 float4-groups
            int row = idx >> 4, g = idx & 15;
            float4 f = *(const float4*)(A + (size_t)(obase + row) * C_ + kt + g * 4);
            __nv_bfloat16 h0 = __float2bfloat16_rn(f.x), h1 = __float2bfloat16_rn(f.y);
            __nv_bfloat16 h2 = __float2bfloat16_rn(f.z), h3 = __float2bfloat16_rn(f.w);
            __nv_bfloat16 l0 = __float2bfloat16_rn(f.x - __bfloat162float(h0));
            __nv_bfloat16 l1 = __float2bfloat16_rn(f.y - __bfloat162float(h1));
            __nv_bfloat16 l2 = __float2bfloat16_rn(f.z - __bfloat162float(h2));
            __nv_bfloat16 l3 = __float2bfloat16_rn(f.w - __bfloat162float(h3));
            *(uint2*)(Ah + row * SGA + g * 4) = make_uint2(pk_bf(h0, h1), pk_bf(h2, h3));
            *(uint2*)(Al + row * SGA + g * 4) = make_uint2(pk_bf(l0, l1), pk_bf(l2, l3));
        }
#pragma unroll
        for (int it = 0; it < 8; it++) {
            int idx = tid + it * 256;
            int row = idx >> 4, g = idx & 15;
            float4 f = make_float4(0.f, 0.f, 0.f, 0.f);
            if (nbase + row < N_)
                f = *(const float4*)(X + (size_t)(nbase + row) * C_ + kt + g * 4);
            __nv_bfloat16 h0 = __float2bfloat16_rn(f.x), h1 = __float2bfloat16_rn(f.y);
            __nv_bfloat16 h2 = __float2bfloat16_rn(f.z), h3 = __float2bfloat16_rn(f.w);
            __nv_bfloat16 l0 = __float2bfloat16_rn(f.x - __bfloat162float(h0));
            __nv_bfloat16 l1 = __float2bfloat16_rn(f.y - __bfloat162float(h1));
            __nv_bfloat16 l2 = __float2bfloat16_rn(f.z - __bfloat162float(h2));
            __nv_bfloat16 l3 = __float2bfloat16_rn(f.w - __bfloat162float(h3));
            *(uint2*)(Xh + row * SGA + g * 4) = make_uint2(pk_bf(h0, h1), pk_bf(h2, h3));
            *(uint2*)(Xl + row * SGA + g * 4) = make_uint2(pk_bf(l0, l1), pk_bf(l2, l3));
        }
        __syncthreads();

#pragma unroll
        for (int ks = 0; ks < 4; ks++) {
            int kk = ks * 16;
            uint32_t ah[2][4], al[2][4];
#pragma unroll
            for (int mi = 0; mi < 2; mi++) {
                int r = wm * 32 + mi * 16 + (lane & 15);
                int cofs = kk + ((lane >> 4) << 3);
                uint32_t off = (uint32_t)(r * SGA + cofs) * 2;
                LDSM4(ah[mi], baAh + off);
                LDSM4(al[mi], baAl + off);
            }
#pragma unroll
            for (int ni = 0; ni < 8; ni++) {
                int rn = wn * 64 + ni * 8 + (lane & 7);
                int cofs = kk + (((lane >> 3) & 1) << 3);
                uint32_t off = (uint32_t)(rn * SGA + cofs) * 2;
                uint32_t bh[2], bl[2];
                LDSM2(bh, baXh + off);
                LDSM2(bl, baXl + off);
#pragma unroll
                for (int mi = 0; mi < 2; mi++) {
                    MMA16816(acc[mi][ni], ah[mi], bh);
                    MMA16816(acc[mi][ni], ah[mi], bl);
                    MMA16816(acc[mi][ni], al[mi], bh);
                }
            }
        }
    }
    __syncthreads();

    // stage accumulators to smem (pad 128 + xor swizzle), then coalesced writes
    float* stage = (float*)dyn;
#pragma unroll
    for (int mi = 0; mi < 2; mi++)
#pragma unroll
        for (int ni = 0; ni < 8; ni++) {
            int m = wm * 32 + mi * 16 + (lane >> 2);
            int n = wn * 64 + ni * 8 + ((lane & 3) << 1);
            *(float2*)&stage[ssw(m, n)] = make_float2(acc[mi][ni][0], acc[mi][ni][1]);
            *(float2*)&stage[ssw(m + 8, n)] = make_float2(acc[mi][ni][2], acc[mi][ni][3]);
        }
    __syncthreads();

    if (!TRANS_OUT) {
        float* outp = g_qkv;
        for (int idx = tid; idx < 128 * 32; idx += 256) {
            int m = idx >> 5, nq = (idx & 31) * 4;
            int n0 = nbase + nq;
            if (n0 < N_) {
                float4 v = *(const float4*)&stage[ssw(m, nq)];
                *(float4*)(outp + ((size_t)b * R1 + obase + m) * N_ + n0) = v;
            }
        }
    } else {
        float* outp = g_projo;
        for (int idx = tid; idx < 128 * 32; idx += 256) {
            int n = idx >> 5, mq = (idx & 31) * 4;
            int ng = nbase + n;
            if (ng < N_) {
                int xw = (((mq >> 2) & 7) << 2);
                float4 v;
                v.x = stage[(mq + 0) * 128 + (n ^ xw)] + bias[obase + mq + 0];
                v.y = stage[(mq + 1) * 128 + (n ^ xw)] + bias[obase + mq + 1];
                v.z = stage[(mq + 2) * 128 + (n ^ xw)] + bias[obase + mq + 2];
                v.w = stage[(mq + 3) * 128 + (n ^ xw)] + bias[obase + mq + 3];
                *(float4*)(outp + ((size_t)b * N_ + ng) * C_ + obase + mq) = v;
            }
        }
    }
}

// ------------------------- 5) flash attention (softmax over keys) ----------
#define FLASH_SMEM_FLOATS (3 * 3072 + 4096 + 1024 + 192)
__global__ void flash_kernel() {
    extern __shared__ __align__(16) float fsm[];
    float* Qs   = fsm;           // [d*64+m]
    float* Ks   = Qs + 3072;     // [d*64+k]
    float* Vs   = Ks + 3072;     // [d*64+k]
    float* Ps   = Vs + 3072;     // [k*64+m]
    float* red  = Ps + 4096;     // [tk*64+m]
    float* mrun = red + 1024;    // 64
    float* lrun = mrun + 64;     // 64
    float* fact = lrun + 64;     // 64

    int mbase = blockIdx.x * 64, h = blockIdx.y, b = blockIdx.z;
    int tid = threadIdx.x;
    int tk = tid >> 4, tm = tid & 15;
    const float* qkb = g_qkv + ((size_t)b * (3 * C_) + (size_t)h * (3 * HD)) * N_;

    for (int idx = tid; idx < HD * 64; idx += 256) {
        int d = idx >> 6, m = idx & 63;
        int mg = mbase + m;
        Qs[idx] = (mg < N_) ? qkb[(size_t)d * N_ + mg] : 0.f;
    }
    if (tid < 64) { mrun[tid] = -1e30f; lrun[tid] = 0.f; }
    ull o2[3][2];
#pragma unroll
    for (int i = 0; i < 3; i++) { o2[i][0] = 0ull; o2[i][1] = 0ull; }
    __syncthreads();

    for (int t = 0; t < 13; t++) {
        int kb = t * 64;
        for (int idx = tid; idx < HD * 64; idx += 256) {
            int d = idx >> 6, kkk = idx & 63;
            int kg = kb + kkk;
            float kv = 0.f, vv = 0.f;
            if (kg < N_) {
                kv = qkb[(size_t)(HD + d) * N_ + kg];
                vv = qkb[(size_t)(2 * HD + d) * N_ + kg];
            }
            Ks[idx] = kv;
            Vs[idx] = vv;
        }
        __syncthreads();

        ull s2[4][2];
#pragma unroll
        for (int a = 0; a < 4; a++) { s2[a][0] = 0ull; s2[a][1] = 0ull; }
#pragma unroll 4
        for (int d = 0; d < HD; d++) {
            float4 kv = *(const float4*)&Ks[d * 64 + tk * 4];
            ulonglong2 q2 = *(const ulonglong2*)&Qs[d * 64 + tm * 4];
            ull k0 = pk2(kv.x, kv.x), k1 = pk2(kv.y, kv.y);
            ull k2 = pk2(kv.z, kv.z), k3 = pk2(kv.w, kv.w);
            FMA2(s2[0][0], k0, q2.x); FMA2(s2[0][1], k0, q2.y);
            FMA2(s2[1][0], k1, q2.x); FMA2(s2[1][1], k1, q2.y);
            FMA2(s2[2][0], k2, q2.x); FMA2(s2[2][1], k2, q2.y);
            FMA2(s2[3][0], k3, q2.x); FMA2(s2[3][1], k3, q2.y);
        }
        float sacc[4][4];
#pragma unroll
        for (int a = 0; a < 4; a++) {
            upk2(s2[a][0], sacc[a][0], sacc[a][1]);
            upk2(s2[a][1], sacc[a][2], sacc[a][3]);
#pragma unroll
            for (int j = 0; j < 4; j++) sacc[a][j] *= ATTN_SCALE;
        }

        float pm[4];
#pragma unroll
        for (int j = 0; j < 4; j++) pm[j] = -1e30f;
#pragma unroll
        for (int a = 0; a < 4; a++) {
            bool valid = (kb + tk * 4 + a) < N_;
#pragma unroll
            for (int j = 0; j < 4; j++)
                if (valid) pm[j] = fmaxf(pm[j], sacc[a][j]);
        }
#pragma unroll
        for (int j = 0; j < 4; j++) red[tk * 64 + tm * 4 + j] = pm[j];
        __syncthreads();
        if (tid < 64) {
            float tmax = -1e30f;
#pragma unroll
            for (int i = 0; i < 16; i++) tmax = fmaxf(tmax, red[i * 64 + tid]);
            float mo = mrun[tid], mn = fmaxf(mo, tmax);
            fact[tid] = __expf(mo - mn);
            mrun[tid] = mn;
        }
        __syncthreads();

        float ps[4];
#pragma unroll
        for (int j = 0; j < 4; j++) {
            float mn = mrun[tm * 4 + j];
            ps[j] = 0.f;
#pragma unroll
            for (int a = 0; a < 4; a++) {
                float p = ((kb + tk * 4 + a) < N_) ? __expf(sacc[a][j] - mn) : 0.f;
                Ps[(tk * 4 + a) * 64 + tm * 4 + j] = p;
                ps[j] += p;
            }
            red[tk * 64 + tm * 4 + j] = ps[j];
        }
        __syncthreads();
        if (tid < 64) {
            float s = 0.f;
#pragma unroll
            for (int i = 0; i < 16; i++) s += red[i * 64 + tid];
            lrun[tid] = lrun[tid] * fact[tid] + s;
        }

        ull f2[2];
        f2[0] = pk2(fact[tm * 4 + 0], fact[tm * 4 + 1]);
        f2[1] = pk2(fact[tm * 4 + 2], fact[tm * 4 + 3]);
#pragma unroll
        for (int i = 0; i < 3; i++) {
            MUL2(o2[i][0], o2[i][0], f2[0]);
            MUL2(o2[i][1], o2[i][1], f2[1]);
        }
#pragma unroll 4
        for (int kk = 0; kk < 64; kk++) {
            float v0 = Vs[(tk * 3 + 0) * 64 + kk];
            float v1 = Vs[(tk * 3 + 1) * 64 + kk];
            float v2 = Vs[(tk * 3 + 2) * 64 + kk];
            ull pv0 = pk2(v0, v0), pv1 = pk2(v1, v1), pv2 = pk2(v2, v2);
            ulonglong2 p2 = *(const ulonglong2*)&Ps[kk * 64 + tm * 4];
            FMA2(o2[0][0], pv0, p2.x); FMA2(o2[0][1], pv0, p2.y);
            FMA2(o2[1][0], pv1, p2.x); FMA2(o2[1][1], pv1, p2.y);
            FMA2(o2[2][0], pv2, p2.x); FMA2(o2[2][1], pv2, p2.y);
        }
        __syncthreads();
    }

    float acc[3][4];
#pragma unroll
    for (int i = 0; i < 3; i++) {
        upk2(o2[i][0], acc[i][0], acc[i][1]);
        upk2(o2[i][1], acc[i][2], acc[i][3]);
    }
#pragma unroll
    for (int j = 0; j < 4; j++) {
        int m = tm * 4 + j;
        float inv = 1.f / lrun[m];
#pragma unroll
        for (int i = 0; i < 3; i++) Ps[m * HD + tk * 3 + i] = acc[i][j] * inv;
    }
    __syncthreads();
    for (int idx = tid; idx < 64 * HD; idx += 256) {
        int m = idx / HD, d = idx % HD;
        int mg = mbase + m;
        if (mg < N_) g_attno[((size_t)b * N_ + mg) * C_ + h * HD + d] = Ps[idx];
    }
}

// ------------------------- 7) scatter stokens back to pixels ---------------
__global__ void scatter_kernel(float* __restrict__ out) {
    __shared__ __align__(16) float out9[C_ * 10];  // [c*10+k]
    __shared__ float aff_s[64 * 9];                // [p*9+k]
    int n = blockIdx.x, b = blockIdx.y;
    int y = n / HH_, x = n % HH_;
    int tid = threadIdx.x;

#pragma unroll
    for (int k = 0; k < 9; k++) {
        int yy = y + k / 3 - 1, xx = x + k % 3 - 1;
        float v = 0.f;
        if (yy >= 0 && yy < HH_ && xx >= 0 && xx < HH_)
            v = g_projo[((size_t)b * N_ + yy * HH_ + xx) * C_ + tid];
        out9[tid * 10 + k] = v;
    }
    size_t abase = ((size_t)b * N_ + n) * 576;
    for (int idx = tid; idx < 576; idx += 384) aff_s[idx] = g_aff[abase + idx];
    __syncthreads();

    int p = tid & 63, cg = tid >> 6;
    float av[9];
#pragma unroll
    for (int k = 0; k < 9; k++) av[k] = aff_s[p * 9 + k];
    ull av2[4];
    av2[0] = pk2(av[0], av[1]);
    av2[1] = pk2(av[2], av[3]);
    av2[2] = pk2(av[4], av[5]);
    av2[3] = pk2(av[6], av[7]);
    int py = p >> 3, px = p & 7;
    float* obase = out + ((size_t)b * C_ * H_ + (size_t)(y * 8 + py)) * H_ + (size_t)x * 8 + px;
    for (int c = cg; c < C_; c += 6) {
        const float* o9 = &out9[c * 10];
        ull o01 = *(const ull*)(o9 + 0);
        ull o23 = *(const ull*)(o9 + 2);
        ull o45 = *(const ull*)(o9 + 4);
        ull o67 = *(const ull*)(o9 + 6);
        ull acc2 = 0ull;
        FMA2(acc2, av2[0], o01);
        FMA2(acc2, av2[1], o23);
        FMA2(acc2, av2[2], o45);
        FMA2(acc2, av2[3], o67);
        float lo, hi;
        upk2(acc2, lo, hi);
        obase[(size_t)c * H_ * H_] = lo + hi + av[8] * o9[8];
    }
}

// ------------------------- launch ------------------------------------------
extern "C" void kernel_launch(void* const* d_in, const int* in_sizes, int n_in,
                              void* d_out, int out_size) {
    const float* xs     = (const float*)d_in[0];
    const float* qkv_w  = (const float*)d_in[2];
    const float* proj_w = (const float*)d_in[3];
    const float* proj_b = (const float*)d_in[4];
    float* out = (float*)d_out;

    cudaFuncSetAttribute(site_kernel, cudaFuncAttributeMaxDynamicSharedMemorySize,
                         SITE_SMEM_FLOATS * (int)sizeof(float));
    cudaFuncSetAttribute(flash_kernel, cudaFuncAttributeMaxDynamicSharedMemorySize,
                         FLASH_SMEM_FLOATS * (int)sizeof(float));
    cudaFuncSetAttribute(gemm_mma<false>, cudaFuncAttributeMaxDynamicSharedMemorySize, GEMM_DSMEM);
    cudaFuncSetAttribute(gemm_mma<true>, cudaFuncAttributeMaxDynamicSharedMemorySize, GEMM_DSMEM);

    pool_kernel<<<dim3(HH_, C_, B_), 224>>>(xs);
    site_kernel<<<dim3(N_, B_), 384, SITE_SMEM_FLOATS * sizeof(float)>>>(xs);
    gather_kernel<<<dim3(N_, B_), C_>>>();
    gemm_mma<false><<<dim3(7, 9, B_), 256, GEMM_DSMEM>>>(qkv_w, nullptr, 3 * C_);
    flash_kernel<<<dim3(13, HEADS, B_), 256, FLASH_SMEM_FLOATS * sizeof(float)>>>();
    gemm_mma<true><<<dim3(7, 3, B_), 256, GEMM_DSMEM>>>(proj_w, proj_b, C_);
    scatter_kernel<<<dim3(N_, B_), 384>>>(out);
}

// round 6
// speedup vs baseline: 1.2125x; 1.0830x over previous
#include <cuda_runtime.h>
#include <cuda_bf16.h>
#include <math.h>
#include <stdint.h>

#define B_    4
#define C_    384
#define H_    224
#define HH_   28
#define N_    784
#define HEADS 8
#define HD    48

#define AFF_SCALE  0.05103103630798288f   /* 384^-0.5 */
#define ATTN_SCALE 0.14433756729740643f   /* 48^-0.5 */

typedef unsigned long long ull;

__device__ __forceinline__ ull pk2(float a, float b) {
    ull r;
    asm("mov.b64 %0, {%1, %2};" : "=l"(r) : "f"(a), "f"(b));
    return r;
}
__device__ __forceinline__ void upk2(ull v, float& a, float& b) {
    asm("mov.b64 {%0, %1}, %2;" : "=f"(a), "=f"(b) : "l"(v));
}
#define FMA2(d, a, b) asm("fma.rn.f32x2 %0, %1, %2, %0;" : "+l"(d) : "l"(a), "l"(b))
#define MUL2(d, a, b) asm("mul.rn.f32x2 %0, %1, %2;" : "=l"(d) : "l"(a), "l"(b))

__device__ __forceinline__ uint32_t smem_u32(const void* p) {
    uint32_t a;
    asm("{ .reg .u64 t; cvta.to.shared.u64 t, %1; cvt.u32.u64 %0, t; }" : "=r"(a) : "l"(p));
    return a;
}
__device__ __forceinline__ uint32_t pk_bf(__nv_bfloat16 a, __nv_bfloat16 b) {
    uint16_t ra = *(uint16_t*)&a, rb = *(uint16_t*)&b;
    return (uint32_t)ra | ((uint32_t)rb << 16);
}

#define LDSM4(r, addr) \
    asm volatile("ldmatrix.sync.aligned.m8n8.x4.shared.b16 {%0,%1,%2,%3}, [%4];" \
                 : "=r"((r)[0]), "=r"((r)[1]), "=r"((r)[2]), "=r"((r)[3]) : "r"(addr))
#define LDSM2(r, addr) \
    asm volatile("ldmatrix.sync.aligned.m8n8.x2.shared.b16 {%0,%1}, [%2];" \
                 : "=r"((r)[0]), "=r"((r)[1]) : "r"(addr))
#define MMA16816(d, a, b) \
    asm volatile("mma.sync.aligned.m16n8k16.row.col.f32.bf16.bf16.f32 " \
                 "{%0,%1,%2,%3}, {%4,%5,%6,%7}, {%8,%9}, {%0,%1,%2,%3};" \
                 : "+f"((d)[0]), "+f"((d)[1]), "+f"((d)[2]), "+f"((d)[3]) \
                 : "r"((a)[0]), "r"((a)[1]), "r"((a)[2]), "r"((a)[3]), \
                   "r"((b)[0]), "r"((b)[1]))

// ------------------------- scratch (device globals, no allocs) -------------
__device__ float g_sf[B_ * N_ * C_];
__device__ float g_aff[B_ * N_ * 64 * 9];
__device__ float g_affsum[B_ * N_ * 9];
__device__ float g_sft_site[B_ * N_ * 9 * C_];
__device__ float g_sftn[B_ * N_ * C_];
__device__ float g_qkv[B_ * 3 * C_ * N_];
__device__ float g_attno[B_ * N_ * C_];
__device__ float g_projo[B_ * N_ * C_];

// ------------------------- 1) 8x8 average pool -----------------------------
__global__ void pool_kernel(const float* __restrict__ xs) {
    int y = blockIdx.x, c = blockIdx.y, b = blockIdx.z;
    int t = threadIdx.x;
    const float* base = xs + ((size_t)(b * C_ + c) * H_ + (size_t)y * 8) * H_;
    float s = 0.f;
#pragma unroll
    for (int dy = 0; dy < 8; dy++) s += base[dy * H_ + t];
    __shared__ float sm[224];
    sm[t] = s;
    __syncthreads();
    if (t < HH_) {
        float acc = 0.f;
#pragma unroll
        for (int i = 0; i < 8; i++) acc += sm[t * 8 + i];
        g_sf[((size_t)b * N_ + (size_t)y * HH_ + t) * C_ + c] = acc * (1.0f / 64.0f);
    }
}

// ------------------------- 2) per-site affinity + aggregation --------------
#define SITE_SMEM_FLOATS (C_ * 65 + C_ * 10 + 6 * 576 + 640)
__global__ void site_kernel(const float* __restrict__ xs) {
    extern __shared__ __align__(16) float sm[];
    float* pix   = sm;
    float* sf9   = pix + C_ * 65;
    float* lpart = sf9 + C_ * 10;
    float* aff_s = lpart + 6 * 576;

    int n = blockIdx.x, b = blockIdx.y;
    int y = n / HH_, x = n % HH_;
    int tid = threadIdx.x;

    const float* xbase = xs + ((size_t)b * C_ * H_ + (size_t)y * 8) * H_ + (size_t)x * 8;
    for (int q = tid; q < C_ * 16; q += 384) {
        int c = q >> 4, r = q & 15;
        int py = r >> 1, pxq = (r & 1) << 2;
        float4 v = *(const float4*)(xbase + ((size_t)c * H_ + py) * H_ + pxq);
        int p = py * 8 + pxq;
        pix[c * 65 + p + 0] = v.x;
        pix[c * 65 + p + 1] = v.y;
        pix[c * 65 + p + 2] = v.z;
        pix[c * 65 + p + 3] = v.w;
    }
#pragma unroll
    for (int k = 0; k < 9; k++) {
        int yy = y + k / 3 - 1, xx = x + k % 3 - 1;
        float v = 0.f;
        if (yy >= 0 && yy < HH_ && xx >= 0 && xx < HH_)
            v = g_sf[((size_t)b * N_ + yy * HH_ + xx) * C_ + tid];
        sf9[tid * 10 + k] = v;
    }
    __syncthreads();

    {
        int p = tid & 63, chunk = tid >> 6;
        ull acc2[4] = {0, 0, 0, 0};
        float acc8 = 0.f;
        for (int cc = 0; cc < 64; cc++) {
            int c = (chunk << 6) + cc;
            float pv = pix[c * 65 + p];
            ull pp = pk2(pv, pv);
            const float* s9 = &sf9[c * 10];
            ull s01 = *(const ull*)(s9 + 0);
            ull s23 = *(const ull*)(s9 + 2);
            ull s45 = *(const ull*)(s9 + 4);
            ull s67 = *(const ull*)(s9 + 6);
            FMA2(acc2[0], pp, s01);
            FMA2(acc2[1], pp, s23);
            FMA2(acc2[2], pp, s45);
            FMA2(acc2[3], pp, s67);
            acc8 = fmaf(pv, s9[8], acc8);
        }
        float l[9];
        upk2(acc2[0], l[0], l[1]);
        upk2(acc2[1], l[2], l[3]);
        upk2(acc2[2], l[4], l[5]);
        upk2(acc2[3], l[6], l[7]);
        l[8] = acc8;
#pragma unroll
        for (int k = 0; k < 9; k++) lpart[chunk * 576 + p * 9 + k] = l[k];
    }
    __syncthreads();
    for (int idx = tid; idx < 576; idx += 384) {
        float s = 0.f;
#pragma unroll
        for (int ch = 0; ch < 6; ch++) s += lpart[ch * 576 + idx];
        int p = idx / 9, k = idx - p * 9;
        aff_s[p * 10 + k] = s * AFF_SCALE;
    }
    __syncthreads();
    if (tid < 64) {
        float m = -1e30f;
#pragma unroll
        for (int k = 0; k < 9; k++) m = fmaxf(m, aff_s[tid * 10 + k]);
        float e[9], ssum = 0.f;
#pragma unroll
        for (int k = 0; k < 9; k++) { e[k] = __expf(aff_s[tid * 10 + k] - m); ssum += e[k]; }
        float inv = 1.f / ssum;
#pragma unroll
        for (int k = 0; k < 9; k++) aff_s[tid * 10 + k] = e[k] * inv;
    }
    __syncthreads();

    size_t abase = ((size_t)b * N_ + n) * 576;
    for (int idx = tid; idx < 576; idx += 384) {
        int p = idx / 9, k = idx - p * 9;
        g_aff[abase + idx] = aff_s[p * 10 + k];
    }
    if (tid < 9) {
        float s = 0.f;
        for (int p = 0; p < 64; p++) s += aff_s[p * 10 + tid];
        g_affsum[((size_t)b * N_ + n) * 9 + tid] = s;
    }

    {
        int c = tid;
        ull acc2[4] = {0, 0, 0, 0};
        float acc8 = 0.f;
        for (int p = 0; p < 64; p++) {
            float pv = pix[c * 65 + p];
            ull pp = pk2(pv, pv);
            const float* a9 = &aff_s[p * 10];
            ull a01 = *(const ull*)(a9 + 0);
            ull a23 = *(const ull*)(a9 + 2);
            ull a45 = *(const ull*)(a9 + 4);
            ull a67 = *(const ull*)(a9 + 6);
            FMA2(acc2[0], pp, a01);
            FMA2(acc2[1], pp, a23);
            FMA2(acc2[2], pp, a45);
            FMA2(acc2[3], pp, a67);
            acc8 = fmaf(pv, a9[8], acc8);
        }
        float r[9];
        upk2(acc2[0], r[0], r[1]);
        upk2(acc2[1], r[2], r[3]);
        upk2(acc2[2], r[4], r[5]);
        upk2(acc2[3], r[6], r[7]);
        r[8] = acc8;
        size_t sbase = ((size_t)b * N_ + n) * 9;
#pragma unroll
        for (int k = 0; k < 9; k++)
            g_sft_site[(sbase + k) * C_ + c] = r[k];
    }
}

// ------------------------- 3) fold3 gather + normalize ---------------------
__global__ void gather_kernel() {
    int n = blockIdx.x, b = blockIdx.y;
    int y = n / HH_, x = n % HH_;
    int c = threadIdx.x;
    float acc = 0.f, asum = 0.f;
#pragma unroll
    for (int k = 0; k < 9; k++) {
        int i = k / 3, j = k % 3;
        int sy = y + 1 - i, sx = x + 1 - j;
        if (sy >= 0 && sy < HH_ && sx >= 0 && sx < HH_) {
            size_t sb = ((size_t)b * N_ + sy * HH_ + sx) * 9 + k;
            acc += g_sft_site[sb * C_ + c];
            asum += g_affsum[sb];
        }
    }
    g_sftn[((size_t)b * N_ + n) * C_ + c] = acc / (asum + 1e-12f);
}

// ------------------------- 4/6) mma.sync bf16-split GEMM -------------------
#define SGA 72
#define GEMM_DSMEM (4 * 128 * SGA * 2)
__device__ __forceinline__ int ssw(int m, int n) { return m * 128 + (n ^ (((m >> 2) & 7) << 2)); }

template <bool TRANS_OUT>
__global__ __launch_bounds__(256) void gemm_mma(const float* __restrict__ A,
                                                const float* __restrict__ bias,
                                                int R1) {
    extern __shared__ __align__(16) char dyn[];
    __nv_bfloat16* Ah = (__nv_bfloat16*)dyn;
    __nv_bfloat16* Al = Ah + 128 * SGA;
    __nv_bfloat16* Xh = Al + 128 * SGA;
    __nv_bfloat16* Xl = Xh + 128 * SGA;

    int b = blockIdx.z;
    int obase = blockIdx.y * 128;
    int nbase = blockIdx.x * 128;
    int tid = threadIdx.x;
    int lane = tid & 31, w = tid >> 5;
    int wm = w & 3, wn = w >> 2;
    const float* X = (TRANS_OUT ? g_attno : g_sftn) + (size_t)b * N_ * C_;

    uint32_t baAh = smem_u32(Ah), baAl = smem_u32(Al);
    uint32_t baXh = smem_u32(Xh), baXl = smem_u32(Xl);

    float acc[2][8][4];
#pragma unroll
    for (int i = 0; i < 2; i++)
#pragma unroll
        for (int j = 0; j < 8; j++)
#pragma unroll
            for (int q = 0; q < 4; q++) acc[i][j][q] = 0.f;

    for (int chunk = 0; chunk < 6; chunk++) {
        int kt = chunk * 64;
        __syncthreads();
#pragma unroll
        for (int it = 0; it < 8; it++) {
            int idx = tid + it * 256;
            int row = idx >> 4, g = idx & 15;
            float4 f = *(const float4*)(A + (size_t)(obase + row) * C_ + kt + g * 4);
            __nv_bfloat16 h0 = __float2bfloat16_rn(f.x), h1 = __float2bfloat16_rn(f.y);
            __nv_bfloat16 h2 = __float2bfloat16_rn(f.z), h3 = __float2bfloat16_rn(f.w);
            __nv_bfloat16 l0 = __float2bfloat16_rn(f.x - __bfloat162float(h0));
            __nv_bfloat16 l1 = __float2bfloat16_rn(f.y - __bfloat162float(h1));
            __nv_bfloat16 l2 = __float2bfloat16_rn(f.z - __bfloat162float(h2));
            __nv_bfloat16 l3 = __float2bfloat16_rn(f.w - __bfloat162float(h3));
            *(uint2*)(Ah + row * SGA + g * 4) = make_uint2(pk_bf(h0, h1), pk_bf(h2, h3));
            *(uint2*)(Al + row * SGA + g * 4) = make_uint2(pk_bf(l0, l1), pk_bf(l2, l3));
        }
#pragma unroll
        for (int it = 0; it < 8; it++) {
            int idx = tid + it * 256;
            int row = idx >> 4, g = idx & 15;
            float4 f = make_float4(0.f, 0.f, 0.f, 0.f);
            if (nbase + row < N_)
                f = *(const float4*)(X + (size_t)(nbase + row) * C_ + kt + g * 4);
            __nv_bfloat16 h0 = __float2bfloat16_rn(f.x), h1 = __float2bfloat16_rn(f.y);
            __nv_bfloat16 h2 = __float2bfloat16_rn(f.z), h3 = __float2bfloat16_rn(f.w);
            __nv_bfloat16 l0 = __float2bfloat16_rn(f.x - __bfloat162float(h0));
            __nv_bfloat16 l1 = __float2bfloat16_rn(f.y - __bfloat162float(h1));
            __nv_bfloat16 l2 = __float2bfloat16_rn(f.z - __bfloat162float(h2));
            __nv_bfloat16 l3 = __float2bfloat16_rn(f.w - __bfloat162float(h3));
            *(uint2*)(Xh + row * SGA + g * 4) = make_uint2(pk_bf(h0, h1), pk_bf(h2, h3));
            *(uint2*)(Xl + row * SGA + g * 4) = make_uint2(pk_bf(l0, l1), pk_bf(l2, l3));
        }
        __syncthreads();

#pragma unroll
        for (int ks = 0; ks < 4; ks++) {
            int kk = ks * 16;
            uint32_t ah[2][4], al[2][4];
#pragma unroll
            for (int mi = 0; mi < 2; mi++) {
                int r = wm * 32 + mi * 16 + (lane & 15);
                int cofs = kk + ((lane >> 4) << 3);
                uint32_t off = (uint32_t)(r * SGA + cofs) * 2;
                LDSM4(ah[mi], baAh + off);
                LDSM4(al[mi], baAl + off);
            }
#pragma unroll
            for (int ni = 0; ni < 8; ni++) {
                int rn = wn * 64 + ni * 8 + (lane & 7);
                int cofs = kk + (((lane >> 3) & 1) << 3);
                uint32_t off = (uint32_t)(rn * SGA + cofs) * 2;
                uint32_t bh[2], bl[2];
                LDSM2(bh, baXh + off);
                LDSM2(bl, baXl + off);
#pragma unroll
                for (int mi = 0; mi < 2; mi++) {
                    MMA16816(acc[mi][ni], ah[mi], bh);
                    MMA16816(acc[mi][ni], ah[mi], bl);
                    MMA16816(acc[mi][ni], al[mi], bh);
                }
            }
        }
    }
    __syncthreads();

    float* stage = (float*)dyn;
#pragma unroll
    for (int mi = 0; mi < 2; mi++)
#pragma unroll
        for (int ni = 0; ni < 8; ni++) {
            int m = wm * 32 + mi * 16 + (lane >> 2);
            int n = wn * 64 + ni * 8 + ((lane & 3) << 1);
            *(float2*)&stage[ssw(m, n)] = make_float2(acc[mi][ni][0], acc[mi][ni][1]);
            *(float2*)&stage[ssw(m + 8, n)] = make_float2(acc[mi][ni][2], acc[mi][ni][3]);
        }
    __syncthreads();

    if (!TRANS_OUT) {
        float* outp = g_qkv;
        for (int idx = tid; idx < 128 * 32; idx += 256) {
            int m = idx >> 5, nq = (idx & 31) * 4;
            int n0 = nbase + nq;
            if (n0 < N_) {
                float4 v = *(const float4*)&stage[ssw(m, nq)];
                *(float4*)(outp + ((size_t)b * R1 + obase + m) * N_ + n0) = v;
            }
        }
    } else {
        float* outp = g_projo;
        for (int idx = tid; idx < 128 * 32; idx += 256) {
            int n = idx >> 5, mq = (idx & 31) * 4;
            int ng = nbase + n;
            if (ng < N_) {
                int xw = (((mq >> 2) & 7) << 2);
                float4 v;
                v.x = stage[(mq + 0) * 128 + (n ^ xw)] + bias[obase + mq + 0];
                v.y = stage[(mq + 1) * 128 + (n ^ xw)] + bias[obase + mq + 1];
                v.z = stage[(mq + 2) * 128 + (n ^ xw)] + bias[obase + mq + 2];
                v.w = stage[(mq + 3) * 128 + (n ^ xw)] + bias[obase + mq + 3];
                *(float4*)(outp + ((size_t)b * N_ + ng) * C_ + obase + mq) = v;
            }
        }
    }
}

// ------------------------- 5) flash attention via mma.sync -----------------
// Per block: 128 queries x one head x one batch. 8 warps, each owns 16 queries.
// S[m][k] = scale * sum_d q[d][m] k[d][k]; softmax over k; O = P V.
// hi/lo bf16 split on both GEMMs (3 mma per fragment).
#define FQS 56   /* Q/K smem stride in halves */
#define FVS 72   /* V smem stride in halves */
// byte offsets in dynamic smem
#define FOFF_QH 0
#define FOFF_QL (FOFF_QH + 128 * FQS * 2)
#define FOFF_KH (FOFF_QL + 128 * FQS * 2)
#define FOFF_KL (FOFF_KH + 64 * FQS * 2)
#define FOFF_VH (FOFF_KL + 64 * FQS * 2)
#define FOFF_VL (FOFF_VH + 48 * FVS * 2)
#define FLASH_DSMEM (FOFF_VL + 48 * FVS * 2)

__global__ __launch_bounds__(256) void flash_mma() {
    extern __shared__ __align__(16) char fdyn[];
    __nv_bfloat16* Qh = (__nv_bfloat16*)(fdyn + FOFF_QH);
    __nv_bfloat16* Ql = (__nv_bfloat16*)(fdyn + FOFF_QL);
    __nv_bfloat16* Kh = (__nv_bfloat16*)(fdyn + FOFF_KH);
    __nv_bfloat16* Kl = (__nv_bfloat16*)(fdyn + FOFF_KL);
    __nv_bfloat16* Vh = (__nv_bfloat16*)(fdyn + FOFF_VH);
    __nv_bfloat16* Vl = (__nv_bfloat16*)(fdyn + FOFF_VL);

    int mbase = blockIdx.x * 128, h = blockIdx.y, b = blockIdx.z;
    int tid = threadIdx.x;
    int lane = tid & 31, w = tid >> 5;
    const float* qkb = g_qkv + ((size_t)b * (3 * C_) + (size_t)h * (3 * HD)) * N_;

    uint32_t baQh = smem_u32(Qh), baQl = smem_u32(Ql);
    uint32_t baKh = smem_u32(Kh), baKl = smem_u32(Kl);
    uint32_t baVh = smem_u32(Vh), baVl = smem_u32(Vl);

    // load Q tile (transpose [d][m] -> [m][d]) with hi/lo split
    for (int idx = tid; idx < HD * 128; idx += 256) {
        int d = idx >> 7, m = idx & 127;
        int mg = mbase + m;
        float f = (mg < N_) ? qkb[(size_t)d * N_ + mg] : 0.f;
        __nv_bfloat16 hh = __float2bfloat16_rn(f);
        __nv_bfloat16 ll = __float2bfloat16_rn(f - __bfloat162float(hh));
        Qh[m * FQS + d] = hh;
        Ql[m * FQS + d] = ll;
    }
    __syncthreads();

    // preload Q fragments (A operand, m16 x k16, 3 k-steps over d=48)
    uint32_t qh[3][4], ql[3][4];
#pragma unroll
    for (int ks = 0; ks < 3; ks++) {
        int r = w * 16 + (lane & 15);
        int cofs = ks * 16 + ((lane >> 4) << 3);
        uint32_t off = (uint32_t)(r * FQS + cofs) * 2;
        LDSM4(qh[ks], baQh + off);
        LDSM4(ql[ks], baQl + off);
    }

    float mrow[2] = {-1e30f, -1e30f};
    float lrow[2] = {0.f, 0.f};
    float o[6][4];
#pragma unroll
    for (int i = 0; i < 6; i++)
#pragma unroll
        for (int j = 0; j < 4; j++) o[i][j] = 0.f;

    for (int t = 0; t < 13; t++) {
        int kb = t * 64;
        __syncthreads();
        // K tile: [d][kg] -> Ks[k][d] (transpose)
        for (int idx = tid; idx < HD * 64; idx += 256) {
            int d = idx >> 6, kk = idx & 63;
            int kg = kb + kk;
            float f = (kg < N_) ? qkb[(size_t)(HD + d) * N_ + kg] : 0.f;
            __nv_bfloat16 hh = __float2bfloat16_rn(f);
            __nv_bfloat16 ll = __float2bfloat16_rn(f - __bfloat162float(hh));
            Kh[kk * FQS + d] = hh;
            Kl[kk * FQS + d] = ll;
        }
        // V tile: [d][kg] -> Vs[d][k] (direct)
        for (int idx = tid; idx < HD * 64; idx += 256) {
            int d = idx >> 6, kk = idx & 63;
            int kg = kb + kk;
            float f = (kg < N_) ? qkb[(size_t)(2 * HD + d) * N_ + kg] : 0.f;
            __nv_bfloat16 hh = __float2bfloat16_rn(f);
            __nv_bfloat16 ll = __float2bfloat16_rn(f - __bfloat162float(hh));
            Vh[d * FVS + kk] = hh;
            Vl[d * FVS + kk] = ll;
        }
        __syncthreads();

        // S = Q K^T  (fragments sacc[nb][4], nb = 8-key blocks)
        float sacc[8][4];
#pragma unroll
        for (int nb = 0; nb < 8; nb++)
#pragma unroll
            for (int j = 0; j < 4; j++) sacc[nb][j] = 0.f;
#pragma unroll
        for (int ks = 0; ks < 3; ks++) {
#pragma unroll
            for (int nbp = 0; nbp < 4; nbp++) {
                int rn = nbp * 16 + ((lane >> 4) & 1) * 8 + (lane & 7);
                int cofs = ks * 16 + ((lane >> 3) & 1) * 8;
                uint32_t off = (uint32_t)(rn * FQS + cofs) * 2;
                uint32_t kbh[4], kbl[4];
                LDSM4(kbh, baKh + off);
                LDSM4(kbl, baKl + off);
                MMA16816(sacc[2 * nbp], qh[ks], kbh);
                MMA16816(sacc[2 * nbp], qh[ks], kbl);
                MMA16816(sacc[2 * nbp], ql[ks], kbh);
                MMA16816(sacc[2 * nbp + 1], qh[ks], kbh + 2);
                MMA16816(sacc[2 * nbp + 1], qh[ks], kbl + 2);
                MMA16816(sacc[2 * nbp + 1], ql[ks], kbh + 2);
            }
        }

        // scale + key mask
#pragma unroll
        for (int nb = 0; nb < 8; nb++)
#pragma unroll
            for (int j = 0; j < 4; j++) sacc[nb][j] *= ATTN_SCALE;
        if (kb + 64 > N_) {
#pragma unroll
            for (int nb = 0; nb < 8; nb++)
#pragma unroll
                for (int j = 0; j < 4; j++) {
                    int kg = kb + nb * 8 + (lane & 3) * 2 + (j & 1);
                    if (kg >= N_) sacc[nb][j] = -1e30f;
                }
        }

        // row max (2 rows per thread: r and r+8)
        float mx0 = -1e30f, mx1 = -1e30f;
#pragma unroll
        for (int nb = 0; nb < 8; nb++) {
            mx0 = fmaxf(mx0, fmaxf(sacc[nb][0], sacc[nb][1]));
            mx1 = fmaxf(mx1, fmaxf(sacc[nb][2], sacc[nb][3]));
        }
        mx0 = fmaxf(mx0, __shfl_xor_sync(0xffffffffu, mx0, 1));
        mx0 = fmaxf(mx0, __shfl_xor_sync(0xffffffffu, mx0, 2));
        mx1 = fmaxf(mx1, __shfl_xor_sync(0xffffffffu, mx1, 1));
        mx1 = fmaxf(mx1, __shfl_xor_sync(0xffffffffu, mx1, 2));
        float mn0 = fmaxf(mrow[0], mx0), mn1 = fmaxf(mrow[1], mx1);
        float f0 = __expf(mrow[0] - mn0), f1 = __expf(mrow[1] - mn1);
        mrow[0] = mn0; mrow[1] = mn1;

        // P = exp(S - m), pack bf16 hi/lo A-fragments, row sums
        uint32_t pah[4][4], pal[4][4];
        float ls0 = 0.f, ls1 = 0.f;
#pragma unroll
        for (int nb = 0; nb < 8; nb++) {
            float p0 = __expf(sacc[nb][0] - mn0);
            float p1 = __expf(sacc[nb][1] - mn0);
            float p2 = __expf(sacc[nb][2] - mn1);
            float p3 = __expf(sacc[nb][3] - mn1);
            ls0 += p0 + p1;
            ls1 += p2 + p3;
            __nv_bfloat16 h0 = __float2bfloat16_rn(p0), h1 = __float2bfloat16_rn(p1);
            __nv_bfloat16 h2 = __float2bfloat16_rn(p2), h3 = __float2bfloat16_rn(p3);
            __nv_bfloat16 e0 = __float2bfloat16_rn(p0 - __bfloat162float(h0));
            __nv_bfloat16 e1 = __float2bfloat16_rn(p1 - __bfloat162float(h1));
            __nv_bfloat16 e2 = __float2bfloat16_rn(p2 - __bfloat162float(h2));
            __nv_bfloat16 e3 = __float2bfloat16_rn(p3 - __bfloat162float(h3));
            int ks2 = nb >> 1, ri = (nb & 1) * 2;
            pah[ks2][ri] = pk_bf(h0, h1);
            pah[ks2][ri + 1] = pk_bf(h2, h3);
            pal[ks2][ri] = pk_bf(e0, e1);
            pal[ks2][ri + 1] = pk_bf(e2, e3);
        }
        ls0 += __shfl_xor_sync(0xffffffffu, ls0, 1);
        ls0 += __shfl_xor_sync(0xffffffffu, ls0, 2);
        ls1 += __shfl_xor_sync(0xffffffffu, ls1, 1);
        ls1 += __shfl_xor_sync(0xffffffffu, ls1, 2);
        lrow[0] = lrow[0] * f0 + ls0;
        lrow[1] = lrow[1] * f1 + ls1;

        // rescale O
#pragma unroll
        for (int db = 0; db < 6; db++) {
            o[db][0] *= f0; o[db][1] *= f0;
            o[db][2] *= f1; o[db][3] *= f1;
        }
        // O += P V
#pragma unroll
        for (int ks = 0; ks < 4; ks++) {
#pragma unroll
            for (int dbp = 0; dbp < 3; dbp++) {
                int rn = dbp * 16 + ((lane >> 4) & 1) * 8 + (lane & 7);
                int cofs = ks * 16 + ((lane >> 3) & 1) * 8;
                uint32_t off = (uint32_t)(rn * FVS + cofs) * 2;
                uint32_t vbh[4], vbl[4];
                LDSM4(vbh, baVh + off);
                LDSM4(vbl, baVl + off);
                MMA16816(o[2 * dbp], pah[ks], vbh);
                MMA16816(o[2 * dbp], pah[ks], vbl);
                MMA16816(o[2 * dbp], pal[ks], vbh);
                MMA16816(o[2 * dbp + 1], pah[ks], vbh + 2);
                MMA16816(o[2 * dbp + 1], pah[ks], vbl + 2);
                MMA16816(o[2 * dbp + 1], pal[ks], vbh + 2);
            }
        }
    }

    // normalize + stage + coalesced write
    __syncthreads();
    float* stage = (float*)fdyn;   // 128 x 52 floats (reuses Q region)
    float li0 = 1.f / lrow[0], li1 = 1.f / lrow[1];
    int r = lane >> 2, cq = (lane & 3) * 2;
#pragma unroll
    for (int db = 0; db < 6; db++) {
        int m0 = w * 16 + r;
        *(float2*)&stage[m0 * 52 + db * 8 + cq] = make_float2(o[db][0] * li0, o[db][1] * li0);
        *(float2*)&stage[(m0 + 8) * 52 + db * 8 + cq] = make_float2(o[db][2] * li1, o[db][3] * li1);
    }
    __syncthreads();
    for (int idx = tid; idx < 128 * 12; idx += 256) {
        int m = idx / 12, dq = (idx % 12) * 4;
        int mg = mbase + m;
        if (mg < N_) {
            float4 v = *(const float4*)&stage[m * 52 + dq];
            *(float4*)(g_attno + ((size_t)b * N_ + mg) * C_ + h * HD + dq) = v;
        }
    }
}

// ------------------------- 7) scatter stokens back to pixels ---------------
__global__ void scatter_kernel(float* __restrict__ out) {
    __shared__ __align__(16) float out9[C_ * 10];
    __shared__ float aff_s[64 * 9];
    int n = blockIdx.x, b = blockIdx.y;
    int y = n / HH_, x = n % HH_;
    int tid = threadIdx.x;

#pragma unroll
    for (int k = 0; k < 9; k++) {
        int yy = y + k / 3 - 1, xx = x + k % 3 - 1;
        float v = 0.f;
        if (yy >= 0 && yy < HH_ && xx >= 0 && xx < HH_)
            v = g_projo[((size_t)b * N_ + yy * HH_ + xx) * C_ + tid];
        out9[tid * 10 + k] = v;
    }
    size_t abase = ((size_t)b * N_ + n) * 576;
    for (int idx = tid; idx < 576; idx += 384) aff_s[idx] = g_aff[abase + idx];
    __syncthreads();

    int p = tid & 63, cg = tid >> 6;
    float av[9];
#pragma unroll
    for (int k = 0; k < 9; k++) av[k] = aff_s[p * 9 + k];
    ull av2[4];
    av2[0] = pk2(av[0], av[1]);
    av2[1] = pk2(av[2], av[3]);
    av2[2] = pk2(av[4], av[5]);
    av2[3] = pk2(av[6], av[7]);
    int py = p >> 3, px = p & 7;
    float* obase = out + ((size_t)b * C_ * H_ + (size_t)(y * 8 + py)) * H_ + (size_t)x * 8 + px;
    for (int c = cg; c < C_; c += 6) {
        const float* o9 = &out9[c * 10];
        ull o01 = *(const ull*)(o9 + 0);
        ull o23 = *(const ull*)(o9 + 2);
        ull o45 = *(const ull*)(o9 + 4);
        ull o67 = *(const ull*)(o9 + 6);
        ull acc2 = 0ull;
        FMA2(acc2, av2[0], o01);
        FMA2(acc2, av2[1], o23);
        FMA2(acc2, av2[2], o45);
        FMA2(acc2, av2[3], o67);
        float lo, hi;
        upk2(acc2, lo, hi);
        obase[(size_t)c * H_ * H_] = lo + hi + av[8] * o9[8];
    }
}

// ------------------------- launch ------------------------------------------
extern "C" void kernel_launch(void* const* d_in, const int* in_sizes, int n_in,
                              void* d_out, int out_size) {
    const float* xs     = (const float*)d_in[0];
    const float* qkv_w  = (const float*)d_in[2];
    const float* proj_w = (const float*)d_in[3];
    const float* proj_b = (const float*)d_in[4];
    float* out = (float*)d_out;

    cudaFuncSetAttribute(site_kernel, cudaFuncAttributeMaxDynamicSharedMemorySize,
                         SITE_SMEM_FLOATS * (int)sizeof(float));
    cudaFuncSetAttribute(flash_mma, cudaFuncAttributeMaxDynamicSharedMemorySize, FLASH_DSMEM);
    cudaFuncSetAttribute(gemm_mma<false>, cudaFuncAttributeMaxDynamicSharedMemorySize, GEMM_DSMEM);
    cudaFuncSetAttribute(gemm_mma<true>, cudaFuncAttributeMaxDynamicSharedMemorySize, GEMM_DSMEM);

    pool_kernel<<<dim3(HH_, C_, B_), 224>>>(xs);
    site_kernel<<<dim3(N_, B_), 384, SITE_SMEM_FLOATS * sizeof(float)>>>(xs);
    gather_kernel<<<dim3(N_, B_), C_>>>();
    gemm_mma<false><<<dim3(7, 9, B_), 256, GEMM_DSMEM>>>(qkv_w, nullptr, 3 * C_);
    flash_mma<<<dim3(7, HEADS, B_), 256, FLASH_DSMEM>>>();
    gemm_mma<true><<<dim3(7, 3, B_), 256, GEMM_DSMEM>>>(proj_w, proj_b, C_);
    scatter_kernel<<<dim3(N_, B_), 384>>>(out);
}

// round 7
// speedup vs baseline: 1.5787x; 1.3020x over previous
#include <cuda_runtime.h>
#include <cuda_bf16.h>
#include <math.h>
#include <stdint.h>

#define B_    4
#define C_    384
#define H_    224
#define HH_   28
#define N_    784
#define HEADS 8
#define HD    48

#define AFF_SCALE  0.05103103630798288f   /* 384^-0.5 */
#define ATTN_SCALE 0.14433756729740643f   /* 48^-0.5 */

typedef unsigned long long ull;

__device__ __forceinline__ ull pk2(float a, float b) {
    ull r;
    asm("mov.b64 %0, {%1, %2};" : "=l"(r) : "f"(a), "f"(b));
    return r;
}
__device__ __forceinline__ void upk2(ull v, float& a, float& b) {
    asm("mov.b64 {%0, %1}, %2;" : "=f"(a), "=f"(b) : "l"(v));
}
#define FMA2(d, a, b) asm("fma.rn.f32x2 %0, %1, %2, %0;" : "+l"(d) : "l"(a), "l"(b))
#define MUL2(d, a, b) asm("mul.rn.f32x2 %0, %1, %2;" : "=l"(d) : "l"(a), "l"(b))

__device__ __forceinline__ uint32_t smem_u32(const void* p) {
    uint32_t a;
    asm("{ .reg .u64 t; cvta.to.shared.u64 t, %1; cvt.u32.u64 %0, t; }" : "=r"(a) : "l"(p));
    return a;
}
__device__ __forceinline__ uint32_t pk_bf(__nv_bfloat16 a, __nv_bfloat16 b) {
    uint16_t ra = *(uint16_t*)&a, rb = *(uint16_t*)&b;
    return (uint32_t)ra | ((uint32_t)rb << 16);
}

#define LDSM4(r, addr) \
    asm volatile("ldmatrix.sync.aligned.m8n8.x4.shared.b16 {%0,%1,%2,%3}, [%4];" \
                 : "=r"((r)[0]), "=r"((r)[1]), "=r"((r)[2]), "=r"((r)[3]) : "r"(addr))
#define LDSM2(r, addr) \
    asm volatile("ldmatrix.sync.aligned.m8n8.x2.shared.b16 {%0,%1}, [%2];" \
                 : "=r"((r)[0]), "=r"((r)[1]) : "r"(addr))
#define MMA16816(d, a, b) \
    asm volatile("mma.sync.aligned.m16n8k16.row.col.f32.bf16.bf16.f32 " \
                 "{%0,%1,%2,%3}, {%4,%5,%6,%7}, {%8,%9}, {%0,%1,%2,%3};" \
                 : "+f"((d)[0]), "+f"((d)[1]), "+f"((d)[2]), "+f"((d)[3]) \
                 : "r"((a)[0]), "r"((a)[1]), "r"((a)[2]), "r"((a)[3]), \
                   "r"((b)[0]), "r"((b)[1]))

__device__ __forceinline__ void cpa16(uint32_t saddr, const void* g) {
    asm volatile("cp.async.cg.shared.global [%0], [%1], 16;" :: "r"(saddr), "l"(g));
}
#define CPA_COMMIT() asm volatile("cp.async.commit_group;" ::: "memory")
#define CPA_WAIT(n)  asm volatile("cp.async.wait_group %0;" :: "n"(n) : "memory")

// ------------------------- scratch (device globals, no allocs) -------------
__device__ float g_sf[B_ * N_ * C_];
__device__ float g_aff[B_ * N_ * 64 * 9];
__device__ float g_affsum[B_ * N_ * 9];
__device__ float g_sft_site[B_ * N_ * 9 * C_];
__device__ float g_sftn[B_ * N_ * C_];
__device__ float g_qkv[B_ * 3 * C_ * N_];
__device__ float g_attno[B_ * N_ * C_];
__device__ float g_projo[B_ * N_ * C_];

// ------------------------- 1) 8x8 average pool -----------------------------
__global__ void pool_kernel(const float* __restrict__ xs) {
    int y = blockIdx.x, c = blockIdx.y, b = blockIdx.z;
    int t = threadIdx.x;
    const float* base = xs + ((size_t)(b * C_ + c) * H_ + (size_t)y * 8) * H_;
    float s = 0.f;
#pragma unroll
    for (int dy = 0; dy < 8; dy++) s += base[dy * H_ + t];
    __shared__ float sm[224];
    sm[t] = s;
    __syncthreads();
    if (t < HH_) {
        float acc = 0.f;
#pragma unroll
        for (int i = 0; i < 8; i++) acc += sm[t * 8 + i];
        g_sf[((size_t)b * N_ + (size_t)y * HH_ + t) * C_ + c] = acc * (1.0f / 64.0f);
    }
}

// ------------------------- 2) site kernel v2: chunked + cp.async pipeline --
// C processed in 4 chunks of 96, double-buffered. Two passes over the tile
// (logits, then aggregation); 2nd pass reloads from L2.
// smem (floats): buf0 | buf1 | sf9[384*10] | stage[3456] | aff[640]
#define CK 96
#define PIXPAD 68
#define BUF_F (CK * PIXPAD)         /* 6528 */
#define S_SF9  (2 * BUF_F)          /* 13056 */
#define S_STG  (S_SF9 + C_ * 10)    /* 16896 */
#define S_AFF  (S_STG + 3456)       /* 20352 */
#define SITE_SMEM_FLOATS (S_AFF + 640)

__global__ __launch_bounds__(384, 2) void site_kernel(const float* __restrict__ xs) {
    extern __shared__ __align__(16) float sm[];
    float* sf9   = sm + S_SF9;
    float* stg   = sm + S_STG;
    float* aff_s = sm + S_AFF;

    int n = blockIdx.x, b = blockIdx.y;
    int y = n / HH_, x = n % HH_;
    int tid = threadIdx.x;
    const float* xbase = xs + ((size_t)b * C_ * H_ + (size_t)y * 8) * H_ + (size_t)x * 8;

    // issue chunk 0 into buf0
    {
        float* buf = sm;
        for (int i = tid; i < CK * 16; i += 384) {
            int cl = i >> 4, r = i & 15;
            int py = r >> 1, px4 = (r & 1) << 2;
            cpa16(smem_u32(&buf[cl * PIXPAD + py * 8 + px4]),
                  xbase + ((size_t)cl * H_ + py) * H_ + px4);
        }
        CPA_COMMIT();
    }
    // sf9 load (overlaps with cp.async)
#pragma unroll
    for (int k = 0; k < 9; k++) {
        int yy = y + k / 3 - 1, xx = x + k % 3 - 1;
        float v = 0.f;
        if (yy >= 0 && yy < HH_ && xx >= 0 && xx < HH_)
            v = g_sf[((size_t)b * N_ + yy * HH_ + xx) * C_ + tid];
        sf9[tid * 10 + k] = v;
    }

    // ---- phase A: logits, pipelined over 4 chunks ----
    int p = tid & 63, csub = tid >> 6;     // 64 pixels x 6 c-subranges (16 c each)
    ull lacc[4] = {0, 0, 0, 0};
    float lacc8 = 0.f;
    for (int ck = 0; ck < 4; ck++) {
        if (ck < 3) {
            float* nb = sm + ((ck + 1) & 1) * BUF_F;
            int cbase = (ck + 1) * CK;
            for (int i = tid; i < CK * 16; i += 384) {
                int cl = i >> 4, r = i & 15;
                int py = r >> 1, px4 = (r & 1) << 2;
                cpa16(smem_u32(&nb[cl * PIXPAD + py * 8 + px4]),
                      xbase + ((size_t)(cbase + cl) * H_ + py) * H_ + px4);
            }
            CPA_COMMIT();
            CPA_WAIT(1);
        } else {
            CPA_WAIT(0);
        }
        __syncthreads();
        const float* buf = sm + (ck & 1) * BUF_F;
#pragma unroll 4
        for (int cc = 0; cc < 16; cc++) {
            int cl = csub * 16 + cc;
            float pv = buf[cl * PIXPAD + p];
            ull pp = pk2(pv, pv);
            const float* s9 = &sf9[(ck * CK + cl) * 10];
            FMA2(lacc[0], pp, *(const ull*)(s9 + 0));
            FMA2(lacc[1], pp, *(const ull*)(s9 + 2));
            FMA2(lacc[2], pp, *(const ull*)(s9 + 4));
            FMA2(lacc[3], pp, *(const ull*)(s9 + 6));
            lacc8 = fmaf(pv, s9[8], lacc8);
        }
        __syncthreads();
    }
    // stage partial logits [csub][p][k]
    {
        float l[9];
        upk2(lacc[0], l[0], l[1]);
        upk2(lacc[1], l[2], l[3]);
        upk2(lacc[2], l[4], l[5]);
        upk2(lacc[3], l[6], l[7]);
        l[8] = lacc8;
#pragma unroll
        for (int k = 0; k < 9; k++) stg[csub * 576 + p * 9 + k] = l[k];
    }
    // prefetch phase-B chunk 0 into buf0 (buffers are free now)
    {
        float* buf = sm;
        for (int i = tid; i < CK * 16; i += 384) {
            int cl = i >> 4, r = i & 15;
            int py = r >> 1, px4 = (r & 1) << 2;
            cpa16(smem_u32(&buf[cl * PIXPAD + py * 8 + px4]),
                  xbase + ((size_t)cl * H_ + py) * H_ + px4);
        }
        CPA_COMMIT();
    }
    __syncthreads();
    // reduce logits across 6 subranges
    for (int idx = tid; idx < 576; idx += 384) {
        float s = 0.f;
#pragma unroll
        for (int ch = 0; ch < 6; ch++) s += stg[ch * 576 + idx];
        int pp = idx / 9, k = idx - pp * 9;
        aff_s[pp * 10 + k] = s * AFF_SCALE;
    }
    __syncthreads();
    // softmax over 9 taps
    if (tid < 64) {
        float m = -1e30f;
#pragma unroll
        for (int k = 0; k < 9; k++) m = fmaxf(m, aff_s[tid * 10 + k]);
        float e[9], ssum = 0.f;
#pragma unroll
        for (int k = 0; k < 9; k++) { e[k] = __expf(aff_s[tid * 10 + k] - m); ssum += e[k]; }
        float inv = 1.f / ssum;
#pragma unroll
        for (int k = 0; k < 9; k++) aff_s[tid * 10 + k] = e[k] * inv;
    }
    __syncthreads();
    // store aff + affsum
    size_t abase = ((size_t)b * N_ + n) * 576;
    for (int idx = tid; idx < 576; idx += 384) {
        int pp = idx / 9, k = idx - pp * 9;
        g_aff[abase + idx] = aff_s[pp * 10 + k];
    }
    if (tid < 9) {
        float s = 0.f;
        for (int pp = 0; pp < 64; pp++) s += aff_s[pp * 10 + tid];
        g_affsum[((size_t)b * N_ + n) * 9 + tid] = s;
    }

    // ---- phase B: aggregation, pipelined over 4 chunks ----
    int cl_t = tid % 96, psub = tid / 96;  // 96 channels x 4 pixel-subranges
    size_t sbase = ((size_t)b * N_ + n) * 9;
    for (int ck = 0; ck < 4; ck++) {
        if (ck < 3) {
            float* nb = sm + ((ck + 1) & 1) * BUF_F;
            int cbase = (ck + 1) * CK;
            for (int i = tid; i < CK * 16; i += 384) {
                int cl = i >> 4, r = i & 15;
                int py = r >> 1, px4 = (r & 1) << 2;
                cpa16(smem_u32(&nb[cl * PIXPAD + py * 8 + px4]),
                      xbase + ((size_t)(cbase + cl) * H_ + py) * H_ + px4);
            }
            CPA_COMMIT();
            CPA_WAIT(1);
        } else {
            CPA_WAIT(0);
        }
        __syncthreads();
        const float* buf = sm + (ck & 1) * BUF_F;
        ull a2[4] = {0, 0, 0, 0};
        float a8 = 0.f;
#pragma unroll
        for (int p4 = 0; p4 < 4; p4++) {
            int pp = psub * 16 + p4 * 4;
            float4 pv4 = *(const float4*)&buf[cl_t * PIXPAD + pp];
            float pv[4] = {pv4.x, pv4.y, pv4.z, pv4.w};
#pragma unroll
            for (int pi = 0; pi < 4; pi++) {
                ull pd = pk2(pv[pi], pv[pi]);
                const float* a9 = &aff_s[(pp + pi) * 10];
                FMA2(a2[0], pd, *(const ull*)(a9 + 0));
                FMA2(a2[1], pd, *(const ull*)(a9 + 2));
                FMA2(a2[2], pd, *(const ull*)(a9 + 4));
                FMA2(a2[3], pd, *(const ull*)(a9 + 6));
                a8 = fmaf(pv[pi], a9[8], a8);
            }
        }
        __syncthreads();   // buf reads done; stage free from previous chunk
        {
            float r[9];
            upk2(a2[0], r[0], r[1]);
            upk2(a2[1], r[2], r[3]);
            upk2(a2[2], r[4], r[5]);
            upk2(a2[3], r[6], r[7]);
            r[8] = a8;
#pragma unroll
            for (int k = 0; k < 9; k++) stg[psub * 864 + k * 96 + cl_t] = r[k];
        }
        __syncthreads();
        for (int idx = tid; idx < 864; idx += 384) {
            float s = stg[idx] + stg[864 + idx] + stg[1728 + idx] + stg[2592 + idx];
            int k = idx / 96, cl = idx - k * 96;
            g_sft_site[(sbase + k) * C_ + ck * CK + cl] = s;
        }
        __syncthreads();
    }
}

// ------------------------- 3) fold3 gather + normalize ---------------------
__global__ void gather_kernel() {
    int n = blockIdx.x, b = blockIdx.y;
    int y = n / HH_, x = n % HH_;
    int c = threadIdx.x;
    float acc = 0.f, asum = 0.f;
#pragma unroll
    for (int k = 0; k < 9; k++) {
        int i = k / 3, j = k % 3;
        int sy = y + 1 - i, sx = x + 1 - j;
        if (sy >= 0 && sy < HH_ && sx >= 0 && sx < HH_) {
            size_t sb = ((size_t)b * N_ + sy * HH_ + sx) * 9 + k;
            acc += g_sft_site[sb * C_ + c];
            asum += g_affsum[sb];
        }
    }
    g_sftn[((size_t)b * N_ + n) * C_ + c] = acc / (asum + 1e-12f);
}

// ------------------------- 4/6) mma.sync bf16-split GEMM -------------------
#define SGA 72
#define GEMM_DSMEM (4 * 128 * SGA * 2)
__device__ __forceinline__ int ssw(int m, int n) { return m * 128 + (n ^ (((m >> 2) & 7) << 2)); }

template <bool TRANS_OUT>
__global__ __launch_bounds__(256, 2) void gemm_mma(const float* __restrict__ A,
                                                   const float* __restrict__ bias,
                                                   int R1) {
    extern __shared__ __align__(16) char dyn[];
    __nv_bfloat16* Ah = (__nv_bfloat16*)dyn;
    __nv_bfloat16* Al = Ah + 128 * SGA;
    __nv_bfloat16* Xh = Al + 128 * SGA;
    __nv_bfloat16* Xl = Xh + 128 * SGA;

    int b = blockIdx.z;
    int obase = blockIdx.y * 128;
    int nbase = blockIdx.x * 128;
    int tid = threadIdx.x;
    int lane = tid & 31, w = tid >> 5;
    int wm = w & 3, wn = w >> 2;
    const float* X = (TRANS_OUT ? g_attno : g_sftn) + (size_t)b * N_ * C_;

    uint32_t baAh = smem_u32(Ah), baAl = smem_u32(Al);
    uint32_t baXh = smem_u32(Xh), baXl = smem_u32(Xl);

    float acc[2][8][4];
#pragma unroll
    for (int i = 0; i < 2; i++)
#pragma unroll
        for (int j = 0; j < 8; j++)
#pragma unroll
            for (int q = 0; q < 4; q++) acc[i][j][q] = 0.f;

    for (int chunk = 0; chunk < 6; chunk++) {
        int kt = chunk * 64;
        __syncthreads();
#pragma unroll
        for (int it = 0; it < 8; it++) {
            int idx = tid + it * 256;
            int row = idx >> 4, g = idx & 15;
            float4 f = *(const float4*)(A + (size_t)(obase + row) * C_ + kt + g * 4);
            __nv_bfloat16 h0 = __float2bfloat16_rn(f.x), h1 = __float2bfloat16_rn(f.y);
            __nv_bfloat16 h2 = __float2bfloat16_rn(f.z), h3 = __float2bfloat16_rn(f.w);
            __nv_bfloat16 l0 = __float2bfloat16_rn(f.x - __bfloat162float(h0));
            __nv_bfloat16 l1 = __float2bfloat16_rn(f.y - __bfloat162float(h1));
            __nv_bfloat16 l2 = __float2bfloat16_rn(f.z - __bfloat162float(h2));
            __nv_bfloat16 l3 = __float2bfloat16_rn(f.w - __bfloat162float(h3));
            *(uint2*)(Ah + row * SGA + g * 4) = make_uint2(pk_bf(h0, h1), pk_bf(h2, h3));
            *(uint2*)(Al + row * SGA + g * 4) = make_uint2(pk_bf(l0, l1), pk_bf(l2, l3));
        }
#pragma unroll
        for (int it = 0; it < 8; it++) {
            int idx = tid + it * 256;
            int row = idx >> 4, g = idx & 15;
            float4 f = make_float4(0.f, 0.f, 0.f, 0.f);
            if (nbase + row < N_)
                f = *(const float4*)(X + (size_t)(nbase + row) * C_ + kt + g * 4);
            __nv_bfloat16 h0 = __float2bfloat16_rn(f.x), h1 = __float2bfloat16_rn(f.y);
            __nv_bfloat16 h2 = __float2bfloat16_rn(f.z), h3 = __float2bfloat16_rn(f.w);
            __nv_bfloat16 l0 = __float2bfloat16_rn(f.x - __bfloat162float(h0));
            __nv_bfloat16 l1 = __float2bfloat16_rn(f.y - __bfloat162float(h1));
            __nv_bfloat16 l2 = __float2bfloat16_rn(f.z - __bfloat162float(h2));
            __nv_bfloat16 l3 = __float2bfloat16_rn(f.w - __bfloat162float(h3));
            *(uint2*)(Xh + row * SGA + g * 4) = make_uint2(pk_bf(h0, h1), pk_bf(h2, h3));
            *(uint2*)(Xl + row * SGA + g * 4) = make_uint2(pk_bf(l0, l1), pk_bf(l2, l3));
        }
        __syncthreads();

#pragma unroll
        for (int ks = 0; ks < 4; ks++) {
            int kk = ks * 16;
            uint32_t ah[2][4], al[2][4];
#pragma unroll
            for (int mi = 0; mi < 2; mi++) {
                int r = wm * 32 + mi * 16 + (lane & 15);
                int cofs = kk + ((lane >> 4) << 3);
                uint32_t off = (uint32_t)(r * SGA + cofs) * 2;
                LDSM4(ah[mi], baAh + off);
                LDSM4(al[mi], baAl + off);
            }
#pragma unroll
            for (int ni = 0; ni < 8; ni++) {
                int rn = wn * 64 + ni * 8 + (lane & 7);
                int cofs = kk + (((lane >> 3) & 1) << 3);
                uint32_t off = (uint32_t)(rn * SGA + cofs) * 2;
                uint32_t bh[2], bl[2];
                LDSM2(bh, baXh + off);
                LDSM2(bl, baXl + off);
#pragma unroll
                for (int mi = 0; mi < 2; mi++) {
                    MMA16816(acc[mi][ni], ah[mi], bh);
                    MMA16816(acc[mi][ni], ah[mi], bl);
                    MMA16816(acc[mi][ni], al[mi], bh);
                }
            }
        }
    }
    __syncthreads();

    float* stage = (float*)dyn;
#pragma unroll
    for (int mi = 0; mi < 2; mi++)
#pragma unroll
        for (int ni = 0; ni < 8; ni++) {
            int m = wm * 32 + mi * 16 + (lane >> 2);
            int n = wn * 64 + ni * 8 + ((lane & 3) << 1);
            *(float2*)&stage[ssw(m, n)] = make_float2(acc[mi][ni][0], acc[mi][ni][1]);
            *(float2*)&stage[ssw(m + 8, n)] = make_float2(acc[mi][ni][2], acc[mi][ni][3]);
        }
    __syncthreads();

    if (!TRANS_OUT) {
        float* outp = g_qkv;
        for (int idx = tid; idx < 128 * 32; idx += 256) {
            int m = idx >> 5, nq = (idx & 31) * 4;
            int n0 = nbase + nq;
            if (n0 < N_) {
                float4 v = *(const float4*)&stage[ssw(m, nq)];
                *(float4*)(outp + ((size_t)b * R1 + obase + m) * N_ + n0) = v;
            }
        }
    } else {
        float* outp = g_projo;
        for (int idx = tid; idx < 128 * 32; idx += 256) {
            int n = idx >> 5, mq = (idx & 31) * 4;
            int ng = nbase + n;
            if (ng < N_) {
                int xw = (((mq >> 2) & 7) << 2);
                float4 v;
                v.x = stage[(mq + 0) * 128 + (n ^ xw)] + bias[obase + mq + 0];
                v.y = stage[(mq + 1) * 128 + (n ^ xw)] + bias[obase + mq + 1];
                v.z = stage[(mq + 2) * 128 + (n ^ xw)] + bias[obase + mq + 2];
                v.w = stage[(mq + 3) * 128 + (n ^ xw)] + bias[obase + mq + 3];
                *(float4*)(outp + ((size_t)b * N_ + ng) * C_ + obase + mq) = v;
            }
        }
    }
}

// ------------------------- 5) flash attention via mma.sync -----------------
#define FQS 56
#define FVS 72
#define FOFF_QH 0
#define FOFF_QL (FOFF_QH + 128 * FQS * 2)
#define FOFF_KH (FOFF_QL + 128 * FQS * 2)
#define FOFF_KL (FOFF_KH + 64 * FQS * 2)
#define FOFF_VH (FOFF_KL + 64 * FQS * 2)
#define FOFF_VL (FOFF_VH + 48 * FVS * 2)
#define FLASH_DSMEM (FOFF_VL + 48 * FVS * 2)

__global__ __launch_bounds__(256) void flash_mma() {
    extern __shared__ __align__(16) char fdyn[];
    __nv_bfloat16* Qh = (__nv_bfloat16*)(fdyn + FOFF_QH);
    __nv_bfloat16* Ql = (__nv_bfloat16*)(fdyn + FOFF_QL);
    __nv_bfloat16* Kh = (__nv_bfloat16*)(fdyn + FOFF_KH);
    __nv_bfloat16* Kl = (__nv_bfloat16*)(fdyn + FOFF_KL);
    __nv_bfloat16* Vh = (__nv_bfloat16*)(fdyn + FOFF_VH);
    __nv_bfloat16* Vl = (__nv_bfloat16*)(fdyn + FOFF_VL);

    int mbase = blockIdx.x * 128, h = blockIdx.y, b = blockIdx.z;
    int tid = threadIdx.x;
    int lane = tid & 31, w = tid >> 5;
    const float* qkb = g_qkv + ((size_t)b * (3 * C_) + (size_t)h * (3 * HD)) * N_;

    uint32_t baQh = smem_u32(Qh), baQl = smem_u32(Ql);
    uint32_t baKh = smem_u32(Kh), baKl = smem_u32(Kl);
    uint32_t baVh = smem_u32(Vh), baVl = smem_u32(Vl);

    for (int idx = tid; idx < HD * 128; idx += 256) {
        int d = idx >> 7, m = idx & 127;
        int mg = mbase + m;
        float f = (mg < N_) ? qkb[(size_t)d * N_ + mg] : 0.f;
        __nv_bfloat16 hh = __float2bfloat16_rn(f);
        __nv_bfloat16 ll = __float2bfloat16_rn(f - __bfloat162float(hh));
        Qh[m * FQS + d] = hh;
        Ql[m * FQS + d] = ll;
    }
    __syncthreads();

    uint32_t qh[3][4], ql[3][4];
#pragma unroll
    for (int ks = 0; ks < 3; ks++) {
        int r = w * 16 + (lane & 15);
        int cofs = ks * 16 + ((lane >> 4) << 3);
        uint32_t off = (uint32_t)(r * FQS + cofs) * 2;
        LDSM4(qh[ks], baQh + off);
        LDSM4(ql[ks], baQl + off);
    }

    float mrow[2] = {-1e30f, -1e30f};
    float lrow[2] = {0.f, 0.f};
    float o[6][4];
#pragma unroll
    for (int i = 0; i < 6; i++)
#pragma unroll
        for (int j = 0; j < 4; j++) o[i][j] = 0.f;

    for (int t = 0; t < 13; t++) {
        int kb = t * 64;
        __syncthreads();
        for (int idx = tid; idx < HD * 64; idx += 256) {
            int d = idx >> 6, kk = idx & 63;
            int kg = kb + kk;
            float f = (kg < N_) ? qkb[(size_t)(HD + d) * N_ + kg] : 0.f;
            __nv_bfloat16 hh = __float2bfloat16_rn(f);
            __nv_bfloat16 ll = __float2bfloat16_rn(f - __bfloat162float(hh));
            Kh[kk * FQS + d] = hh;
            Kl[kk * FQS + d] = ll;
        }
        for (int idx = tid; idx < HD * 64; idx += 256) {
            int d = idx >> 6, kk = idx & 63;
            int kg = kb + kk;
            float f = (kg < N_) ? qkb[(size_t)(2 * HD + d) * N_ + kg] : 0.f;
            __nv_bfloat16 hh = __float2bfloat16_rn(f);
            __nv_bfloat16 ll = __float2bfloat16_rn(f - __bfloat162float(hh));
            Vh[d * FVS + kk] = hh;
            Vl[d * FVS + kk] = ll;
        }
        __syncthreads();

        float sacc[8][4];
#pragma unroll
        for (int nb = 0; nb < 8; nb++)
#pragma unroll
            for (int j = 0; j < 4; j++) sacc[nb][j] = 0.f;
#pragma unroll
        for (int ks = 0; ks < 3; ks++) {
#pragma unroll
            for (int nbp = 0; nbp < 4; nbp++) {
                int rn = nbp * 16 + ((lane >> 4) & 1) * 8 + (lane & 7);
                int cofs = ks * 16 + ((lane >> 3) & 1) * 8;
                uint32_t off = (uint32_t)(rn * FQS + cofs) * 2;
                uint32_t kbh[4], kbl[4];
                LDSM4(kbh, baKh + off);
                LDSM4(kbl, baKl + off);
                MMA16816(sacc[2 * nbp], qh[ks], kbh);
                MMA16816(sacc[2 * nbp], qh[ks], kbl);
                MMA16816(sacc[2 * nbp], ql[ks], kbh);
                MMA16816(sacc[2 * nbp + 1], qh[ks], kbh + 2);
                MMA16816(sacc[2 * nbp + 1], qh[ks], kbl + 2);
                MMA16816(sacc[2 * nbp + 1], ql[ks], kbh + 2);
            }
        }

#pragma unroll
        for (int nb = 0; nb < 8; nb++)
#pragma unroll
            for (int j = 0; j < 4; j++) sacc[nb][j] *= ATTN_SCALE;
        if (kb + 64 > N_) {
#pragma unroll
            for (int nb = 0; nb < 8; nb++)
#pragma unroll
                for (int j = 0; j < 4; j++) {
                    int kg = kb + nb * 8 + (lane & 3) * 2 + (j & 1);
                    if (kg >= N_) sacc[nb][j] = -1e30f;
                }
        }

        float mx0 = -1e30f, mx1 = -1e30f;
#pragma unroll
        for (int nb = 0; nb < 8; nb++) {
            mx0 = fmaxf(mx0, fmaxf(sacc[nb][0], sacc[nb][1]));
            mx1 = fmaxf(mx1, fmaxf(sacc[nb][2], sacc[nb][3]));
        }
        mx0 = fmaxf(mx0, __shfl_xor_sync(0xffffffffu, mx0, 1));
        mx0 = fmaxf(mx0, __shfl_xor_sync(0xffffffffu, mx0, 2));
        mx1 = fmaxf(mx1, __shfl_xor_sync(0xffffffffu, mx1, 1));
        mx1 = fmaxf(mx1, __shfl_xor_sync(0xffffffffu, mx1, 2));
        float mn0 = fmaxf(mrow[0], mx0), mn1 = fmaxf(mrow[1], mx1);
        float f0 = __expf(mrow[0] - mn0), f1 = __expf(mrow[1] - mn1);
        mrow[0] = mn0; mrow[1] = mn1;

        uint32_t pah[4][4], pal[4][4];
        float ls0 = 0.f, ls1 = 0.f;
#pragma unroll
        for (int nb = 0; nb < 8; nb++) {
            float p0 = __expf(sacc[nb][0] - mn0);
            float p1 = __expf(sacc[nb][1] - mn0);
            float p2 = __expf(sacc[nb][2] - mn1);
            float p3 = __expf(sacc[nb][3] - mn1);
            ls0 += p0 + p1;
            ls1 += p2 + p3;
            __nv_bfloat16 h0 = __float2bfloat16_rn(p0), h1 = __float2bfloat16_rn(p1);
            __nv_bfloat16 h2 = __float2bfloat16_rn(p2), h3 = __float2bfloat16_rn(p3);
            __nv_bfloat16 e0 = __float2bfloat16_rn(p0 - __bfloat162float(h0));
            __nv_bfloat16 e1 = __float2bfloat16_rn(p1 - __bfloat162float(h1));
            __nv_bfloat16 e2 = __float2bfloat16_rn(p2 - __bfloat162float(h2));
            __nv_bfloat16 e3 = __float2bfloat16_rn(p3 - __bfloat162float(h3));
            int ks2 = nb >> 1, ri = (nb & 1) * 2;
            pah[ks2][ri] = pk_bf(h0, h1);
            pah[ks2][ri + 1] = pk_bf(h2, h3);
            pal[ks2][ri] = pk_bf(e0, e1);
            pal[ks2][ri + 1] = pk_bf(e2, e3);
        }
        ls0 += __shfl_xor_sync(0xffffffffu, ls0, 1);
        ls0 += __shfl_xor_sync(0xffffffffu, ls0, 2);
        ls1 += __shfl_xor_sync(0xffffffffu, ls1, 1);
        ls1 += __shfl_xor_sync(0xffffffffu, ls1, 2);
        lrow[0] = lrow[0] * f0 + ls0;
        lrow[1] = lrow[1] * f1 + ls1;

#pragma unroll
        for (int db = 0; db < 6; db++) {
            o[db][0] *= f0; o[db][1] *= f0;
            o[db][2] *= f1; o[db][3] *= f1;
        }
#pragma unroll
        for (int ks = 0; ks < 4; ks++) {
#pragma unroll
            for (int dbp = 0; dbp < 3; dbp++) {
                int rn = dbp * 16 + ((lane >> 4) & 1) * 8 + (lane & 7);
                int cofs = ks * 16 + ((lane >> 3) & 1) * 8;
                uint32_t off = (uint32_t)(rn * FVS + cofs) * 2;
                uint32_t vbh[4], vbl[4];
                LDSM4(vbh, baVh + off);
                LDSM4(vbl, baVl + off);
                MMA16816(o[2 * dbp], pah[ks], vbh);
                MMA16816(o[2 * dbp], pah[ks], vbl);
                MMA16816(o[2 * dbp], pal[ks], vbh);
                MMA16816(o[2 * dbp + 1], pah[ks], vbh + 2);
                MMA16816(o[2 * dbp + 1], pah[ks], vbl + 2);
                MMA16816(o[2 * dbp + 1], pal[ks], vbh + 2);
            }
        }
    }

    __syncthreads();
    float* stage = (float*)fdyn;
    float li0 = 1.f / lrow[0], li1 = 1.f / lrow[1];
    int r = lane >> 2, cq = (lane & 3) * 2;
#pragma unroll
    for (int db = 0; db < 6; db++) {
        int m0 = w * 16 + r;
        *(float2*)&stage[m0 * 52 + db * 8 + cq] = make_float2(o[db][0] * li0, o[db][1] * li0);
        *(float2*)&stage[(m0 + 8) * 52 + db * 8 + cq] = make_float2(o[db][2] * li1, o[db][3] * li1);
    }
    __syncthreads();
    for (int idx = tid; idx < 128 * 12; idx += 256) {
        int m = idx / 12, dq = (idx % 12) * 4;
        int mg = mbase + m;
        if (mg < N_) {
            float4 v = *(const float4*)&stage[m * 52 + dq];
            *(float4*)(g_attno + ((size_t)b * N_ + mg) * C_ + h * HD + dq) = v;
        }
    }
}

// ------------------------- 7) scatter stokens back to pixels ---------------
__global__ void scatter_kernel(float* __restrict__ out) {
    __shared__ __align__(16) float out9[C_ * 10];
    __shared__ float aff_s[64 * 9];
    int n = blockIdx.x, b = blockIdx.y;
    int y = n / HH_, x = n % HH_;
    int tid = threadIdx.x;

#pragma unroll
    for (int k = 0; k < 9; k++) {
        int yy = y + k / 3 - 1, xx = x + k % 3 - 1;
        float v = 0.f;
        if (yy >= 0 && yy < HH_ && xx >= 0 && xx < HH_)
            v = g_projo[((size_t)b * N_ + yy * HH_ + xx) * C_ + tid];
        out9[tid * 10 + k] = v;
    }
    size_t abase = ((size_t)b * N_ + n) * 576;
    for (int idx = tid; idx < 576; idx += 384) aff_s[idx] = g_aff[abase + idx];
    __syncthreads();

    int p = tid & 63, cg = tid >> 6;
    float av[9];
#pragma unroll
    for (int k = 0; k < 9; k++) av[k] = aff_s[p * 9 + k];
    ull av2[4];
    av2[0] = pk2(av[0], av[1]);
    av2[1] = pk2(av[2], av[3]);
    av2[2] = pk2(av[4], av[5]);
    av2[3] = pk2(av[6], av[7]);
    int py = p >> 3, px = p & 7;
    float* obase = out + ((size_t)b * C_ * H_ + (size_t)(y * 8 + py)) * H_ + (size_t)x * 8 + px;
    for (int c = cg; c < C_; c += 6) {
        const float* o9 = &out9[c * 10];
        ull o01 = *(const ull*)(o9 + 0);
        ull o23 = *(const ull*)(o9 + 2);
        ull o45 = *(const ull*)(o9 + 4);
        ull o67 = *(const ull*)(o9 + 6);
        ull acc2 = 0ull;
        FMA2(acc2, av2[0], o01);
        FMA2(acc2, av2[1], o23);
        FMA2(acc2, av2[2], o45);
        FMA2(acc2, av2[3], o67);
        float lo, hi;
        upk2(acc2, lo, hi);
        obase[(size_t)c * H_ * H_] = lo + hi + av[8] * o9[8];
    }
}

// ------------------------- launch ------------------------------------------
extern "C" void kernel_launch(void* const* d_in, const int* in_sizes, int n_in,
                              void* d_out, int out_size) {
    const float* xs     = (const float*)d_in[0];
    const float* qkv_w  = (const float*)d_in[2];
    const float* proj_w = (const float*)d_in[3];
    const float* proj_b = (const float*)d_in[4];
    float* out = (float*)d_out;

    cudaFuncSetAttribute(site_kernel, cudaFuncAttributeMaxDynamicSharedMemorySize,
                         SITE_SMEM_FLOATS * (int)sizeof(float));
    cudaFuncSetAttribute(flash_mma, cudaFuncAttributeMaxDynamicSharedMemorySize, FLASH_DSMEM);
    cudaFuncSetAttribute(gemm_mma<false>, cudaFuncAttributeMaxDynamicSharedMemorySize, GEMM_DSMEM);
    cudaFuncSetAttribute(gemm_mma<true>, cudaFuncAttributeMaxDynamicSharedMemorySize, GEMM_DSMEM);

    pool_kernel<<<dim3(HH_, C_, B_), 224>>>(xs);
    site_kernel<<<dim3(N_, B_), 384, SITE_SMEM_FLOATS * sizeof(float)>>>(xs);
    gather_kernel<<<dim3(N_, B_), C_>>>();
    gemm_mma<false><<<dim3(7, 9, B_), 256, GEMM_DSMEM>>>(qkv_w, nullptr, 3 * C_);
    flash_mma<<<dim3(7, HEADS, B_), 256, FLASH_DSMEM>>>();
    gemm_mma<true><<<dim3(7, 3, B_), 256, GEMM_DSMEM>>>(proj_w, proj_b, C_);
    scatter_kernel<<<dim3(N_, B_), 384>>>(out);
}